// round 12
// baseline (speedup 1.0000x reference)
#include <cuda_runtime.h>
#include <cuda_bf16.h>
#include <cstdint>

#define NN  16384
#define DD  32
#define INPD 256
#define UU  128
#define RR  8
#define ENTT 8

// ---------------- scratch (device globals: no allocation allowed) ----------------
__device__ float g_center[NN * UU];                    // (N, U) fp32
__device__ __nv_bfloat16 g_center_h[NN * UU];          // center hi plane
__device__ __nv_bfloat16 g_center_l[NN * UU];          // center lo plane
__device__ float g_qr[NN * RR * UU];                   // (N, R*U) fp32
__device__ __nv_bfloat16 g_sh[NN * RR * UU];           // s hi plane  (N, 1024)
__device__ __nv_bfloat16 g_sl[NN * RR * UU];           // s lo plane
__device__ __nv_bfloat16 g_nsh[NN * INPD];             // node_state hi plane (N, 256)
__device__ __nv_bfloat16 g_nsl[NN * INPD];             // node_state lo plane
__device__ __nv_bfloat16 g_pwTh[ENTT * UU * INPD];     // pe_w^T hi: [e][u=128][i=256]
__device__ __nv_bfloat16 g_pwTl[ENTT * UU * INPD];     // pe_w^T lo
__device__ float g_T[RR * UU * UU];                    // T[r] = rel[r] @ k_w
__device__ float g_S[RR * UU * UU];                    // S[r] = rel[r] @ v_w
__device__ __nv_bfloat16 g_BkTh[RR * UU * UU];         // Bk2^T hi: [1024][128]
__device__ __nv_bfloat16 g_BkTl[RR * UU * UU];         // Bk2^T lo
__device__ __nv_bfloat16 g_BvTh[RR * UU * UU];         // Bv2^T hi: [128][1024]
__device__ __nv_bfloat16 g_BvTl[RR * UU * UU];         // Bv2^T lo
__device__ int   g_cnt[ENTT];
__device__ int   g_lists[ENTT * NN];
__device__ int   g_bar;                                 // monotone barrier ticket

// ======================= warp-level bf16 MMA (HMMA path, plain sm_103) =======================
__device__ __forceinline__ void mma_bf16(float* d,
                                         uint32_t a0, uint32_t a1, uint32_t a2, uint32_t a3,
                                         uint32_t b0, uint32_t b1)
{
    asm volatile(
        "mma.sync.aligned.m16n8k16.row.col.f32.bf16.bf16.f32 "
        "{%0,%1,%2,%3}, {%4,%5,%6,%7}, {%8,%9}, {%0,%1,%2,%3};"
        : "+f"(d[0]), "+f"(d[1]), "+f"(d[2]), "+f"(d[3])
        : "r"(a0), "r"(a1), "r"(a2), "r"(a3), "r"(b0), "r"(b1));
}

__device__ __forceinline__ void cp16(uint32_t dst, const void* src, int sz) {
    asm volatile("cp.async.ca.shared.global [%0], [%1], 16, %2;"
                 :: "r"(dst), "l"(src), "r"(sz) : "memory");
}
#define CP_COMMIT() asm volatile("cp.async.commit_group;" ::: "memory")
#define CP_WAIT1()  asm volatile("cp.async.wait_group 1;" ::: "memory")

// XOR swizzle at 16B-chunk granularity (rows are 16 words of packed bf16x2).
__device__ __forceinline__ int swz(int row, int c) {
    return row * 16 + ((c ^ (row & 3) ^ ((row >> 2) & 1)) << 2);
}

__device__ __forceinline__ uint32_t pack_split(float x, float y, uint32_t& lo) {
    __nv_bfloat16 hx = __float2bfloat16(x), hy = __float2bfloat16(y);
    __nv_bfloat16 lx = __float2bfloat16(x - __bfloat162float(hx));
    __nv_bfloat16 ly = __float2bfloat16(y - __bfloat162float(hy));
    lo = ((uint32_t)__bfloat16_as_ushort(ly) << 16) | __bfloat16_as_ushort(lx);
    return ((uint32_t)__bfloat16_as_ushort(hy) << 16) | __bfloat16_as_ushort(hx);
}

// ======================= pre-split bf16 GEMM (3-stage cp.async pipeline) =======================
// C[MT x 128] = A @ B^T, split-bf16 3-pass; A planes [M][K], BT planes [N][K] bf16.
// Optional row gather via rowlists/cnts (per blockIdx.z; B planes get z*sBz).
// Epilogue: fp32 C (+ optional hi/lo planes Ch/Cl), +bias, relu, +addsrc.
#define STGW(MT) (2*(MT)*16 + 2*128*16)
#define SMEM_PRE(MT) (512 + 3 * STGW(MT) * 4)

template<int MT>
__device__ __forceinline__ void issue_chunk(
    uint32_t stg_base, int kc,
    const __nv_bfloat16* Ah, const __nv_bfloat16* Al,
    const __nv_bfloat16* Bh, const __nv_bfloat16* Bl,
    int K, int n0, const int* rowidx, int tid)
{
#pragma unroll
    for (int it = 0; it < MT / 64; it++) {
        int lin = tid + it * 256;
        int row = lin >> 2, c = lin & 3;
        int ar = rowidx[row];
        int wd = swz(row, c);
        long off = (long)((ar >= 0) ? ar : 0) * K + kc * 32 + c * 8;
        int sz = (ar >= 0) ? 16 : 0;
        cp16(stg_base + wd * 4, Ah + off, sz);
        cp16(stg_base + (MT * 16 + wd) * 4, Al + off, sz);
    }
#pragma unroll
    for (int it = 0; it < 2; it++) {
        int lin = tid + it * 256;
        int row = lin >> 2, c = lin & 3;
        int wd = swz(row, c);
        long off = (long)(n0 + row) * K + kc * 32 + c * 8;
        cp16(stg_base + (2 * MT * 16 + wd) * 4, Bh + off, 16);
        cp16(stg_base + (2 * MT * 16 + 128 * 16 + wd) * 4, Bl + off, 16);
    }
}

template<int MT>
__global__ __launch_bounds__(256, 2) void mma_pre(
    const __nv_bfloat16* __restrict__ Ah, const __nv_bfloat16* __restrict__ Al,
    const __nv_bfloat16* __restrict__ Bh, const __nv_bfloat16* __restrict__ Bl,
    int K, long sBz,
    const int* __restrict__ rowlists, const int* __restrict__ cnts,
    float* __restrict__ C, int ldc,
    __nv_bfloat16* __restrict__ Ch, __nv_bfloat16* __restrict__ Cl,
    const float* __restrict__ bias, const float* __restrict__ addsrc, int do_relu)
{
    constexpr int NI = MT / 32;
    extern __shared__ char smem[];
    int* rowidx = (int*)smem;
    uint32_t* smw = (uint32_t*)(smem + 512);
    uint32_t sb0 = (uint32_t)__cvta_generic_to_shared(smem) + 512;

    const int tid  = threadIdx.x;
    const int lane = tid & 31;
    const int w    = tid >> 5;
    const int wm   = w >> 2;
    const int wn   = w & 3;
    const int q    = lane >> 2;
    const int s4   = lane & 3;
    const int m0   = blockIdx.x * MT;
    const int n0   = blockIdx.y * 128;
    const int z    = blockIdx.z;

    const int* rl = nullptr;
    if (rowlists) {
        int rows = cnts[z];
        if (m0 >= rows) return;
        rl = rowlists + z * NN;
        if (tid < MT) {
            int g = m0 + tid;
            rowidx[tid] = (g < rows) ? rl[g] : -1;
        }
    } else {
        if (tid < MT) rowidx[tid] = m0 + tid;
    }
    Bh += (long)z * sBz;
    Bl += (long)z * sBz;
    __syncthreads();

    float acc[NI][4][4];
#pragma unroll
    for (int i = 0; i < NI; i++)
#pragma unroll
        for (int j = 0; j < 4; j++)
#pragma unroll
            for (int r = 0; r < 4; r++) acc[i][j][r] = 0.f;

    const int nk = K / 32;
    issue_chunk<MT>(sb0, 0, Ah, Al, Bh, Bl, K, n0, rowidx, tid);
    CP_COMMIT();
    issue_chunk<MT>(sb0 + STGW(MT) * 4, 1, Ah, Al, Bh, Bl, K, n0, rowidx, tid);
    CP_COMMIT();

    for (int kt = 0; kt < nk; kt++) {
        CP_WAIT1();
        __syncthreads();

        const uint32_t* stg = smw + (kt % 3) * STGW(MT);
        const uint32_t* pAh = stg;
        const uint32_t* pAl = stg + MT * 16;
        const uint32_t* pBh = stg + 2 * MT * 16;
        const uint32_t* pBl = pBh + 128 * 16;

#pragma unroll
        for (int st = 0; st < 2; st++) {
            uint32_t a[NI][4];
#pragma unroll
            for (int p = 0; p < 3; p++) {
                const uint32_t* pA = (p == 2) ? pAl : pAh;
                const uint32_t* pB = (p == 1) ? pBl : pBh;
                if (p != 1) {
#pragma unroll
                    for (int i = 0; i < NI; i++) {
                        int r = wm * (MT / 2) + i * 16 + q;
                        a[i][0] = pA[swz(r, st * 2) + s4];
                        a[i][1] = pA[swz(r + 8, st * 2) + s4];
                        a[i][2] = pA[swz(r, st * 2 + 1) + s4];
                        a[i][3] = pA[swz(r + 8, st * 2 + 1) + s4];
                    }
                }
#pragma unroll
                for (int j = 0; j < 4; j++) {
                    int c = wn * 32 + j * 8 + q;
                    uint32_t b0 = pB[swz(c, st * 2) + s4];
                    uint32_t b1 = pB[swz(c, st * 2 + 1) + s4];
#pragma unroll
                    for (int i = 0; i < NI; i++)
                        mma_bf16(acc[i][j], a[i][0], a[i][1], a[i][2], a[i][3], b0, b1);
                }
            }
        }
        if (kt + 2 < nk)
            issue_chunk<MT>(sb0 + ((kt + 2) % 3) * STGW(MT) * 4, kt + 2,
                            Ah, Al, Bh, Bl, K, n0, rowidx, tid);
        CP_COMMIT();
    }

    // ---- epilogue (scatter via rowidx; optional hi/lo plane outputs) ----
#pragma unroll
    for (int i = 0; i < NI; i++) {
        int lr0 = wm * (MT / 2) + i * 16 + q;
#pragma unroll
        for (int j = 0; j < 4; j++) {
            int cc = n0 + wn * 32 + j * 8 + s4 * 2;
            float bx = 0.f, by = 0.f;
            if (bias) { bx = bias[cc]; by = bias[cc + 1]; }
#pragma unroll
            for (int hrow = 0; hrow < 2; hrow++) {
                int rr = rowidx[lr0 + hrow * 8];
                if (rr < 0) continue;
                float vx = acc[i][j][hrow * 2 + 0] + bx;
                float vy = acc[i][j][hrow * 2 + 1] + by;
                if (do_relu) { vx = fmaxf(vx, 0.f); vy = fmaxf(vy, 0.f); }
                if (addsrc) {
                    const float2 av = *reinterpret_cast<const float2*>(addsrc + (long)rr * ldc + cc);
                    vx += av.x; vy += av.y;
                }
                *reinterpret_cast<float2*>(C + (long)rr * ldc + cc) = make_float2(vx, vy);
                if (Ch) {
                    uint32_t pl, ph = pack_split(vx, vy, pl);
                    reinterpret_cast<uint32_t*>(Ch)[((long)rr * ldc + cc) >> 1] = ph;
                    reinterpret_cast<uint32_t*>(Cl)[((long)rr * ldc + cc) >> 1] = pl;
                }
            }
        }
    }
}

// ---------------- 32x128x128 SIMT tile (prep GEMMs) ----------------
__device__ __forceinline__ void gemm32(const float* __restrict__ A,
                                       const float* __restrict__ B,
                                       float* __restrict__ Cf32,
                                       float alpha, int transB,
                                       __nv_bfloat16* oh, __nv_bfloat16* ol,
                                       int o_ld, int rowbase, int colbase)
{
    __shared__ float As[32][33];
    __shared__ float Bs[32][128];
    int tid = threadIdx.x, tx = tid & 15, ty = tid >> 4;
    float acc[2][8];
#pragma unroll
    for (int i = 0; i < 2; i++)
#pragma unroll
        for (int j = 0; j < 8; j++) acc[i][j] = 0.f;

    for (int kt = 0; kt < 128; kt += 32) {
#pragma unroll
        for (int j = 0; j < 4; j++) {
            int lin = tid + j * 256;
            int lr = lin >> 5, lc = lin & 31;
            As[lr][lc] = A[lr * 128 + kt + lc];
        }
#pragma unroll
        for (int j = 0; j < 16; j++) {
            int lin = tid + j * 256;
            int br = lin >> 7, bc = lin & 127;
            Bs[br][bc] = transB ? B[bc * 128 + kt + br] : B[(kt + br) * 128 + bc];
        }
        __syncthreads();
#pragma unroll
        for (int kk = 0; kk < 32; kk++) {
            float bv[8];
#pragma unroll
            for (int j = 0; j < 8; j++) bv[j] = Bs[kk][tx + 16 * j];
#pragma unroll
            for (int i = 0; i < 2; i++) {
                float av = As[ty * 2 + i][kk];
#pragma unroll
                for (int j = 0; j < 8; j++) acc[i][j] += av * bv[j];
            }
        }
        __syncthreads();
    }
    if (Cf32) {
#pragma unroll
        for (int i = 0; i < 2; i++)
#pragma unroll
            for (int j = 0; j < 8; j++)
                Cf32[(ty * 2 + i) * 128 + tx + 16 * j] = acc[i][j] * alpha;
    } else {
#pragma unroll
        for (int i = 0; i < 2; i++) {
            int gr = rowbase + ty * 2 + i;
#pragma unroll
            for (int j = 0; j < 8; j++) {
                int gc = colbase + tx + 16 * j;
                float v = acc[i][j] * alpha;
                __nv_bfloat16 h = __float2bfloat16(v);
                oh[(long)gc * o_ld + gr] = h;
                ol[(long)gc * o_ld + gr] = __float2bfloat16(v - __bfloat162float(h));
            }
        }
    }
}

// prep_fused: phase1 (T/S) -> global barrier -> phase2 (BkT/BvT planes). 64 blocks.
__global__ __launch_bounds__(256) void prep_fused(const float* __restrict__ rel_w,
                                                  const float* __restrict__ k_w,
                                                  const float* __restrict__ v_w,
                                                  const float* __restrict__ q_w,
                                                  const float* __restrict__ fc_w)
{
    int b = blockIdx.x;
    int j = b >> 2, sub = b & 3;
    int tid = threadIdx.x;

    {   // phase 1
        int r = j & 7, ph = j >> 3;
        const float* A = rel_w + r * (UU * UU) + sub * 32 * UU;
        const float* B = ph ? v_w : k_w;
        float* C = (ph ? g_S : g_T) + r * (UU * UU) + sub * 32 * UU;
        gemm32(A, B, C, 1.f, 0, nullptr, nullptr, 0, 0, 0);
    }

    // global barrier (monotone ticket: 64 arrivals per replay, no reset needed)
    __syncthreads();
    if (tid == 0) {
        __threadfence();
        int ticket = atomicAdd(&g_bar, 1);
        int target = ((ticket >> 6) + 1) << 6;
        while (atomicAdd(&g_bar, 0) < target) __nanosleep(64);
    }
    __syncthreads();

    {   // phase 2
        if (j < 8) {
            int r = j;
            gemm32(q_w + sub * 32 * UU, g_T + r * (UU * UU), nullptr,
                   1.f / 128.f, 1, g_BkTh, g_BkTl, 128, sub * 32, r * UU);
        } else {
            int r = j - 8;
            gemm32(g_S + r * (UU * UU) + sub * 32 * UU, fc_w, nullptr,
                   1.f, 0, g_BvTh, g_BvTl, 1024, r * UU + sub * 32, 0);
        }
    }
}

// splitns_part: node_state planes | pe_w^T planes | entity partition (independent work).
__global__ __launch_bounds__(256) void splitns_part(const float* __restrict__ node_state,
                                                    const float* __restrict__ pe_w,
                                                    const int* __restrict__ point_enc)
{
    int b = blockIdx.x, tid = threadIdx.x;
    if (b < 512) {
        const float4* ns4 = (const float4*)node_state;
        uint2* oh = (uint2*)g_nsh;
        uint2* ol = (uint2*)g_nsl;
#pragma unroll
        for (int i = 0; i < 8; i++) {
            long g4 = (long)b * 2048 + i * 256 + tid;
            float4 v = ns4[g4];
            uint2 hh, ll;
            hh.x = pack_split(v.x, v.y, ll.x);
            hh.y = pack_split(v.z, v.w, ll.y);
            oh[g4] = hh;
            ol[g4] = ll;
        }
    } else if (b < 544) {
        int b2 = b - 512;
        int e = b2 >> 2, qd = b2 & 3;
        const float* src = pe_w + (long)e * INPD * UU;
        __nv_bfloat16* dh = g_pwTh + (long)e * UU * INPD;
        __nv_bfloat16* dl = g_pwTl + (long)e * UU * INPD;
#pragma unroll
        for (int t = 0; t < 32; t++) {
            int lin = tid + t * 256;
            int il = lin >> 7, u = lin & 127;
            int i = qd * 64 + il;
            float v = src[i * UU + u];
            __nv_bfloat16 h = __float2bfloat16(v);
            dh[(long)u * INPD + i] = h;
            dl[(long)u * INPD + i] = __float2bfloat16(v - __bfloat162float(h));
        }
    } else {
        int n = (b - 544) * 256 + tid;
        int e = point_enc[n];
        int pos = atomicAdd(&g_cnt[e], 1);
        g_lists[e * NN + pos] = n;
    }
}

// ---------------- fused gather / score / softmax / weighted-scatter ----------------
__global__ __launch_bounds__(128) void edge_kernel(const int* __restrict__ adjacency,
                                                   const int* __restrict__ relation)
{
    __shared__ float xs[DD][UU];
    __shared__ float aw[RR][DD];
    __shared__ float scores[DD];
    __shared__ int adjs[DD];
    __shared__ int rels[DD];

    int n = blockIdx.x;
    int tid = threadIdx.x, lane = tid & 31, w = tid >> 5;

    if (blockIdx.x == 0 && tid < ENTT) g_cnt[tid] = 0;   // reset for next graph replay

    if (tid < DD) {
        adjs[tid] = adjacency[n * DD + tid];
        rels[tid] = relation[n * DD + tid];
    }
    __syncthreads();

#pragma unroll
    for (int i = 0; i < 8; i++) {
        int d = w * 8 + i;
        int idx = adjs[d];
        float4 v = (idx > 0)
            ? reinterpret_cast<const float4*>(g_center + (idx - 1) * UU)[lane]
            : make_float4(0.f, 0.f, 0.f, 0.f);
        reinterpret_cast<float4*>(&xs[d][0])[lane] = v;
    }
    __syncwarp();

    const float* qbase = g_qr + n * (RR * UU);
#pragma unroll
    for (int i = 0; i < 8; i++) {
        int d = w * 8 + i;
        int r = rels[d];
        const float* q = qbase + r * UU;
        float s = 0.f;
#pragma unroll
        for (int k2 = 0; k2 < 4; k2++) {
            int c = lane + 32 * k2;
            s += q[c] * xs[d][c];
        }
#pragma unroll
        for (int off = 16; off > 0; off >>= 1) s += __shfl_xor_sync(0xffffffffu, s, off);
        if (lane == 0) scores[d] = (r == 0) ? -1e9f : s;
    }
    __syncthreads();

    if (w == 0) {
        float v = scores[lane];
        float m = v;
#pragma unroll
        for (int off = 16; off > 0; off >>= 1) m = fmaxf(m, __shfl_xor_sync(0xffffffffu, m, off));
        float e = __expf(v - m);
        float sum = e;
#pragma unroll
        for (int off = 16; off > 0; off >>= 1) sum += __shfl_xor_sync(0xffffffffu, sum, off);
        float a = e / sum;
        int r = rels[lane];
#pragma unroll
        for (int rr = 0; rr < RR; rr++) aw[rr][lane] = (r == rr) ? a : 0.f;
    }
    __syncthreads();

    float acc[RR];
#pragma unroll
    for (int r = 0; r < RR; r++) acc[r] = 0.f;
#pragma unroll
    for (int d = 0; d < DD; d++) {
        float x = xs[d][tid];
#pragma unroll
        for (int r = 0; r < RR; r++) acc[r] += aw[r][d] * x;
    }
    __nv_bfloat16* sph = g_sh + (long)n * (RR * UU) + tid;
    __nv_bfloat16* spl = g_sl + (long)n * (RR * UU) + tid;
#pragma unroll
    for (int r = 0; r < RR; r++) {
        float v = acc[r];
        __nv_bfloat16 h = __float2bfloat16(v);
        sph[r * UU] = h;
        spl[r * UU] = __float2bfloat16(v - __bfloat162float(h));
    }
}

// ---------------- launch ----------------
extern "C" void kernel_launch(void* const* d_in, const int* in_sizes, int n_in,
                              void* d_out, int out_size)
{
    const float* node_state = (const float*)d_in[0];
    const int*   adjacency  = (const int*)d_in[1];
    const int*   point_enc  = (const int*)d_in[2];
    const int*   relation   = (const int*)d_in[3];
    const float* pe_w       = (const float*)d_in[4];
    const float* rel_w      = (const float*)d_in[5];
    const float* q_w        = (const float*)d_in[6];
    const float* k_w        = (const float*)d_in[7];
    const float* v_w        = (const float*)d_in[8];
    const float* fc_w       = (const float*)d_in[9];
    const float* fc_b       = (const float*)d_in[10];
    float* out = (float*)d_out;

    float *p_center, *p_qr;
    __nv_bfloat16 *p_ch, *p_cl, *p_sh, *p_sl, *p_nsh, *p_nsl, *p_pwh, *p_pwl;
    __nv_bfloat16 *p_bkh, *p_bkl, *p_bvh, *p_bvl;
    int *p_cnt, *p_lists;
    cudaGetSymbolAddress((void**)&p_center, g_center);
    cudaGetSymbolAddress((void**)&p_qr,     g_qr);
    cudaGetSymbolAddress((void**)&p_ch,     g_center_h);
    cudaGetSymbolAddress((void**)&p_cl,     g_center_l);
    cudaGetSymbolAddress((void**)&p_sh,     g_sh);
    cudaGetSymbolAddress((void**)&p_sl,     g_sl);
    cudaGetSymbolAddress((void**)&p_nsh,    g_nsh);
    cudaGetSymbolAddress((void**)&p_nsl,    g_nsl);
    cudaGetSymbolAddress((void**)&p_pwh,    g_pwTh);
    cudaGetSymbolAddress((void**)&p_pwl,    g_pwTl);
    cudaGetSymbolAddress((void**)&p_bkh,    g_BkTh);
    cudaGetSymbolAddress((void**)&p_bkl,    g_BkTl);
    cudaGetSymbolAddress((void**)&p_bvh,    g_BvTh);
    cudaGetSymbolAddress((void**)&p_bvl,    g_BvTl);
    cudaGetSymbolAddress((void**)&p_cnt,    g_cnt);
    cudaGetSymbolAddress((void**)&p_lists,  g_lists);

    cudaFuncSetAttribute(mma_pre<128>, cudaFuncAttributeMaxDynamicSharedMemorySize, SMEM_PRE(128));
    cudaFuncSetAttribute(mma_pre<64>,  cudaFuncAttributeMaxDynamicSharedMemorySize, SMEM_PRE(64));

    // 1. split node_state + pe_w^T planes + entity partition (one fused launch)
    splitns_part<<<608, 256>>>(node_state, pe_w, point_enc);

    // 2. prep: T/S -> (barrier) -> BkT/BvT planes (one fused launch)
    prep_fused<<<64, 256>>>(rel_w, k_w, v_w, q_w, fc_w);

    // 3. center = gathered pre-split GEMM (K=256); emits fp32 + hi/lo planes
    mma_pre<128><<<dim3(32, 1, 8), 256, SMEM_PRE(128)>>>(
        p_nsh, p_nsl, p_pwh, p_pwl, INPD, (long)UU * INPD,
        p_lists, p_cnt,
        p_center, 128, p_ch, p_cl,
        nullptr, nullptr, 0);

    // 4. qr = center @ Bk2   (N x 1024, K=128)
    mma_pre<128><<<dim3(128, 8, 1), 256, SMEM_PRE(128)>>>(
        p_ch, p_cl, p_bkh, p_bkl, 128, 0L,
        nullptr, nullptr,
        p_qr, 1024, nullptr, nullptr,
        nullptr, nullptr, 0);

    // 5. fused gather / scores / softmax / per-relation weighted sums -> s planes
    edge_kernel<<<NN, 128>>>(adjacency, relation);

    // 6. out = center + relu(s @ Bv2 + fc_b)   (N x 128, K=1024)
    mma_pre<64><<<dim3(256, 1, 1), 256, SMEM_PRE(64)>>>(
        p_sh, p_sl, p_bvh, p_bvl, 1024, 0L,
        nullptr, nullptr,
        out, 128, nullptr, nullptr,
        fc_b, p_center, 1);
}

// round 13
// speedup vs baseline: 1.1390x; 1.1390x over previous
#include <cuda_runtime.h>
#include <cuda_bf16.h>
#include <cstdint>

#define NN  16384
#define DD  32
#define INPD 256
#define UU  128
#define RR  8
#define ENTT 8

// ---------------- scratch (device globals: no allocation allowed) ----------------
__device__ float g_center[NN * UU];                    // (N, U) fp32
__device__ __nv_bfloat16 g_center_h[NN * UU];          // center hi plane
__device__ __nv_bfloat16 g_center_l[NN * UU];          // center lo plane
__device__ float g_qr[NN * RR * UU];                   // (N, R*U) fp32
__device__ __nv_bfloat16 g_sh[NN * RR * UU];           // s hi plane  (N, 1024)
__device__ __nv_bfloat16 g_sl[NN * RR * UU];           // s lo plane
__device__ float g_T[RR * UU * UU];                    // T[r] = rel[r] @ k_w
__device__ float g_S[RR * UU * UU];                    // S[r] = rel[r] @ v_w
__device__ __nv_bfloat16 g_BkTh[RR * UU * UU];         // Bk2^T hi: [1024][128]
__device__ __nv_bfloat16 g_BkTl[RR * UU * UU];         // Bk2^T lo
__device__ __nv_bfloat16 g_BvTh[RR * UU * UU];         // Bv2^T hi: [128][1024]
__device__ __nv_bfloat16 g_BvTl[RR * UU * UU];         // Bv2^T lo
__device__ int   g_cnt[ENTT];
__device__ int   g_lists[ENTT * NN];
__device__ int   g_bar;                                 // monotone barrier ticket

// ======================= warp-level bf16 MMA (HMMA path, plain sm_103) =======================
__device__ __forceinline__ void mma_bf16(float* d,
                                         uint32_t a0, uint32_t a1, uint32_t a2, uint32_t a3,
                                         uint32_t b0, uint32_t b1)
{
    asm volatile(
        "mma.sync.aligned.m16n8k16.row.col.f32.bf16.bf16.f32 "
        "{%0,%1,%2,%3}, {%4,%5,%6,%7}, {%8,%9}, {%0,%1,%2,%3};"
        : "+f"(d[0]), "+f"(d[1]), "+f"(d[2]), "+f"(d[3])
        : "r"(a0), "r"(a1), "r"(a2), "r"(a3), "r"(b0), "r"(b1));
}

__device__ __forceinline__ void ldm_x4(uint32_t& r0, uint32_t& r1, uint32_t& r2, uint32_t& r3,
                                       uint32_t addr)
{
    asm volatile("ldmatrix.sync.aligned.m8n8.x4.shared.b16 {%0,%1,%2,%3}, [%4];"
                 : "=r"(r0), "=r"(r1), "=r"(r2), "=r"(r3) : "r"(addr));
}

__device__ __forceinline__ void cp16(uint32_t dst, const void* src, int sz) {
    asm volatile("cp.async.ca.shared.global [%0], [%1], 16, %2;"
                 :: "r"(dst), "l"(src), "r"(sz) : "memory");
}
#define CP_COMMIT() asm volatile("cp.async.commit_group;" ::: "memory")
#define CP_WAIT1()  asm volatile("cp.async.wait_group 1;" ::: "memory")
#define CP_WAIT0()  asm volatile("cp.async.wait_group 0;" ::: "memory")

// XOR swizzle at 16B-chunk granularity (rows are 16 words of packed bf16x2).
__device__ __forceinline__ int swz(int row, int c) {
    return row * 16 + ((c ^ (row & 3) ^ ((row >> 2) & 1)) << 2);
}

__device__ __forceinline__ uint32_t pack_split(float x, float y, uint32_t& lo) {
    __nv_bfloat16 hx = __float2bfloat16(x), hy = __float2bfloat16(y);
    __nv_bfloat16 lx = __float2bfloat16(x - __bfloat162float(hx));
    __nv_bfloat16 ly = __float2bfloat16(y - __bfloat162float(hy));
    lo = ((uint32_t)__bfloat16_as_ushort(ly) << 16) | __bfloat16_as_ushort(lx);
    return ((uint32_t)__bfloat16_as_ushort(hy) << 16) | __bfloat16_as_ushort(hx);
}

// ======================= pre-split bf16 GEMM (3-stage cp.async + ldmatrix) ====================
// C[MT x 128] = A @ B^T, split-bf16 3-pass; A planes [M][K], BT planes [N][K] bf16.
#define STGW(MT) (2*(MT)*16 + 2*128*16)
#define SMEM_PRE(MT) (3 * STGW(MT) * 4)

template<int MT>
__device__ __forceinline__ void issue_chunk(
    uint32_t stg_base, int kc,
    const __nv_bfloat16* Ah, const __nv_bfloat16* Al,
    const __nv_bfloat16* Bh, const __nv_bfloat16* Bl,
    int K, int m0, int n0, int tid)
{
#pragma unroll
    for (int it = 0; it < MT / 64; it++) {
        int lin = tid + it * 256;
        int row = lin >> 2, c = lin & 3;
        int wd = swz(row, c);
        long off = (long)(m0 + row) * K + kc * 32 + c * 8;
        cp16(stg_base + wd * 4, Ah + off, 16);
        cp16(stg_base + (MT * 16 + wd) * 4, Al + off, 16);
    }
#pragma unroll
    for (int it = 0; it < 2; it++) {
        int lin = tid + it * 256;
        int row = lin >> 2, c = lin & 3;
        int wd = swz(row, c);
        long off = (long)(n0 + row) * K + kc * 32 + c * 8;
        cp16(stg_base + (2 * MT * 16 + wd) * 4, Bh + off, 16);
        cp16(stg_base + (2 * MT * 16 + 128 * 16 + wd) * 4, Bl + off, 16);
    }
}

template<int MT>
__global__ __launch_bounds__(256, 2) void mma_pre(
    const __nv_bfloat16* __restrict__ Ah, const __nv_bfloat16* __restrict__ Al,
    const __nv_bfloat16* __restrict__ Bh, const __nv_bfloat16* __restrict__ Bl,
    int K,
    float* __restrict__ C, int ldc,
    const float* __restrict__ bias, const float* __restrict__ addsrc, int do_relu)
{
    constexpr int NI = MT / 32;
    extern __shared__ char smem[];
    uint32_t sb0 = (uint32_t)__cvta_generic_to_shared(smem);

    const int tid  = threadIdx.x;
    const int lane = tid & 31;
    const int w    = tid >> 5;
    const int wm   = w >> 2;
    const int wn   = w & 3;
    const int q    = lane >> 2;
    const int s4   = lane & 3;
    const int lrow = lane & 7;          // ldmatrix row-provider index
    const int seg  = lane >> 3;         // ldmatrix matrix-segment index
    const int m0   = blockIdx.x * MT;
    const int n0   = blockIdx.y * 128;

    float acc[NI][4][4];
#pragma unroll
    for (int i = 0; i < NI; i++)
#pragma unroll
        for (int j = 0; j < 4; j++)
#pragma unroll
            for (int r = 0; r < 4; r++) acc[i][j][r] = 0.f;

    const int nk = K / 32;
    issue_chunk<MT>(sb0, 0, Ah, Al, Bh, Bl, K, m0, n0, tid);
    CP_COMMIT();
    issue_chunk<MT>(sb0 + STGW(MT) * 4, 1, Ah, Al, Bh, Bl, K, m0, n0, tid);
    CP_COMMIT();

    for (int kt = 0; kt < nk; kt++) {
        CP_WAIT1();
        __syncthreads();

        const uint32_t stg = sb0 + (kt % 3) * STGW(MT) * 4;
        const uint32_t oAh = stg;
        const uint32_t oAl = stg + MT * 16 * 4;
        const uint32_t oBh = stg + 2 * MT * 16 * 4;
        const uint32_t oBl = oBh + 128 * 16 * 4;

#pragma unroll
        for (int st = 0; st < 2; st++) {
            const int c0 = st * 2;
            // per-thread ldmatrix source coordinates
            const int achk = c0 + (seg >> 1);           // A: seg0,1 -> klo ; seg2,3 -> khi
            const int aoff = lrow + (seg & 1) * 8;      //    seg0,2 -> rows ; seg1,3 -> rows+8
            const int bchk = c0 + (seg & 1);            // B: seg0,2 -> klo ; seg1,3 -> khi
            const int bsel = (seg >> 1);                //    seg0,1 -> j ; seg2,3 -> j+1

            uint32_t aH[NI][4], bH[4][2], bL[4][2];

            // --- load B-hi (2 x4 for j-pairs (0,1),(2,3)) ---
#pragma unroll
            for (int jp = 0; jp < 2; jp++) {
                int bcol = wn * 32 + (jp * 2 + bsel) * 8 + lrow;
                ldm_x4(bH[jp * 2][0], bH[jp * 2][1], bH[jp * 2 + 1][0], bH[jp * 2 + 1][1],
                       oBh + swz(bcol, bchk) * 4);
            }
            // --- load A-hi (NI x4) ---
#pragma unroll
            for (int i = 0; i < NI; i++) {
                int arow = wm * (MT / 2) + i * 16 + aoff;
                ldm_x4(aH[i][0], aH[i][1], aH[i][2], aH[i][3], oAh + swz(arow, achk) * 4);
            }
            // --- pass 0: Ahi * Bhi ---
#pragma unroll
            for (int j = 0; j < 4; j++)
#pragma unroll
                for (int i = 0; i < NI; i++)
                    mma_bf16(acc[i][j], aH[i][0], aH[i][1], aH[i][2], aH[i][3],
                             bH[j][0], bH[j][1]);
            // --- load B-lo; pass 1: Ahi * Blo ---
#pragma unroll
            for (int jp = 0; jp < 2; jp++) {
                int bcol = wn * 32 + (jp * 2 + bsel) * 8 + lrow;
                ldm_x4(bL[jp * 2][0], bL[jp * 2][1], bL[jp * 2 + 1][0], bL[jp * 2 + 1][1],
                       oBl + swz(bcol, bchk) * 4);
            }
#pragma unroll
            for (int j = 0; j < 4; j++)
#pragma unroll
                for (int i = 0; i < NI; i++)
                    mma_bf16(acc[i][j], aH[i][0], aH[i][1], aH[i][2], aH[i][3],
                             bL[j][0], bL[j][1]);
            // --- load A-lo (overwrite aH); pass 2: Alo * Bhi ---
#pragma unroll
            for (int i = 0; i < NI; i++) {
                int arow = wm * (MT / 2) + i * 16 + aoff;
                ldm_x4(aH[i][0], aH[i][1], aH[i][2], aH[i][3], oAl + swz(arow, achk) * 4);
            }
#pragma unroll
            for (int j = 0; j < 4; j++)
#pragma unroll
                for (int i = 0; i < NI; i++)
                    mma_bf16(acc[i][j], aH[i][0], aH[i][1], aH[i][2], aH[i][3],
                             bH[j][0], bH[j][1]);
        }
        if (kt + 2 < nk)
            issue_chunk<MT>(sb0 + ((kt + 2) % 3) * STGW(MT) * 4, kt + 2,
                            Ah, Al, Bh, Bl, K, m0, n0, tid);
        CP_COMMIT();
    }

    // ---- epilogue ----
#pragma unroll
    for (int i = 0; i < NI; i++) {
        int r0 = m0 + wm * (MT / 2) + i * 16 + q;
#pragma unroll
        for (int j = 0; j < 4; j++) {
            int cc = n0 + wn * 32 + j * 8 + s4 * 2;
            float bx = 0.f, by = 0.f;
            if (bias) { bx = bias[cc]; by = bias[cc + 1]; }
#pragma unroll
            for (int hrow = 0; hrow < 2; hrow++) {
                int rr = r0 + hrow * 8;
                float vx = acc[i][j][hrow * 2 + 0] + bx;
                float vy = acc[i][j][hrow * 2 + 1] + by;
                if (do_relu) { vx = fmaxf(vx, 0.f); vy = fmaxf(vy, 0.f); }
                if (addsrc) {
                    const float2 av = *reinterpret_cast<const float2*>(addsrc + (long)rr * ldc + cc);
                    vx += av.x; vy += av.y;
                }
                *reinterpret_cast<float2*>(C + (long)rr * ldc + cc) = make_float2(vx, vy);
            }
        }
    }
}

// ======================= fp32-input pipelined MMA (center only: gather + split) ==============
#define SROW 17
#define SMEM_MMA (512 + 128*256 + 32768 + 2*128*SROW*4 + 2*128*SROW*4)

__global__ __launch_bounds__(256) void mma_gemm_f32(
    const float* __restrict__ A, int lda,
    const float* __restrict__ B, int ldb, long sBz,
    float* __restrict__ C, int ldc, int K,
    const int* __restrict__ rowlists, const int* __restrict__ cnts,
    __nv_bfloat16* __restrict__ Ch, __nv_bfloat16* __restrict__ Cl)
{
    constexpr int MT = 128;
    constexpr int NI = 4;
    extern __shared__ char smem[];
    int*      rowidx = (int*)smem;
    float*    rawA   = (float*)(smem + 512);
    float*    rawB   = (float*)(smem + 512 + MT * 256);
    uint32_t* sAb    = (uint32_t*)(smem + 512 + MT * 256 + 32768);
    uint32_t* sBb    = sAb + 2 * MT * SROW;

    const int tid  = threadIdx.x;
    const int lane = tid & 31;
    const int w    = tid >> 5;
    const int wm   = w >> 2;
    const int wn   = w & 3;
    const int m0   = blockIdx.x * MT;
    const int n0   = blockIdx.y * 128;
    const int z    = blockIdx.z;

    int rows = cnts[z];
    if (m0 >= rows) return;
    const int* rl = rowlists + z * NN;
    B += z * sBz;

    if (tid < MT) {
        int g = m0 + tid;
        rowidx[tid] = (g < rows) ? rl[g] : -1;
    }
    __syncthreads();

    float acc[NI][4][4];
#pragma unroll
    for (int i = 0; i < NI; i++)
#pragma unroll
        for (int j = 0; j < 4; j++)
#pragma unroll
            for (int r = 0; r < 4; r++) acc[i][j][r] = 0.f;

    const int nk = K / 32;
    {
#pragma unroll
        for (int it = 0; it < NI; it++) {
            int lin = tid + it * 256;
            int row = lin >> 3, f4 = lin & 7;
            int ar = rowidx[row];
            const float* src = (ar >= 0) ? (A + (long)ar * lda + f4 * 4) : A;
            cp16((uint32_t)__cvta_generic_to_shared(rawA + row * 32 + f4 * 4), src,
                 (ar >= 0) ? 16 : 0);
        }
#pragma unroll
        for (int it = 0; it < 4; it++) {
            int lin = tid + it * 256;
            int kk = lin >> 5, n4 = (lin & 31) * 4;
            cp16((uint32_t)__cvta_generic_to_shared(rawB + kk * 128 + n4),
                 B + (long)kk * ldb + n0 + n4, 16);
        }
        CP_COMMIT();
    }

    for (int kt = 0; kt < nk; kt++) {
        const int cur = kt & 1;
        if (kt + 1 < nk) {
            const int nxt = cur ^ 1;
            const int k0 = (kt + 1) * 32;
#pragma unroll
            for (int it = 0; it < NI; it++) {
                int lin = tid + it * 256;
                int row = lin >> 3, f4 = lin & 7;
                int ar = rowidx[row];
                const float* src = (ar >= 0) ? (A + (long)ar * lda + k0 + f4 * 4) : A;
                cp16((uint32_t)__cvta_generic_to_shared(rawA + nxt * MT * 32 + row * 32 + f4 * 4),
                     src, (ar >= 0) ? 16 : 0);
            }
#pragma unroll
            for (int it = 0; it < 4; it++) {
                int lin = tid + it * 256;
                int kk = lin >> 5, n4 = (lin & 31) * 4;
                cp16((uint32_t)__cvta_generic_to_shared(rawB + nxt * 4096 + kk * 128 + n4),
                     B + (long)(k0 + kk) * ldb + n0 + n4, 16);
            }
            CP_COMMIT();
            CP_WAIT1();
        } else {
            CP_WAIT0();
        }
        __syncthreads();

        const float* rA = rawA + cur * MT * 32;
#pragma unroll
        for (int it = 0; it < NI; it++) {
            int lin = tid + it * 256;
            int row = lin >> 3, f4 = lin & 7;
            float4 v = *reinterpret_cast<const float4*>(rA + row * 32 + f4 * 4);
            uint32_t l0, l1;
            uint32_t h0 = pack_split(v.x, v.y, l0);
            uint32_t h1 = pack_split(v.z, v.w, l1);
            int idx = row * SROW + f4 * 2;
            sAb[idx]                 = h0;
            sAb[idx + 1]             = h1;
            sAb[MT * SROW + idx]     = l0;
            sAb[MT * SROW + idx + 1] = l1;
        }
        const float* rB = rawB + cur * 4096;
#pragma unroll
        for (int it = 0; it < 4; it++) {
            int lin = tid + it * 256;
            int kk = lin >> 5, n4 = (lin & 31) * 4;
            float4 v = *reinterpret_cast<const float4*>(rB + kk * 128 + n4);
            float vv[4] = {v.x, v.y, v.z, v.w};
            __nv_bfloat16* pH = reinterpret_cast<__nv_bfloat16*>(sBb);
            __nv_bfloat16* pL = reinterpret_cast<__nv_bfloat16*>(sBb + 128 * SROW);
#pragma unroll
            for (int j = 0; j < 4; j++) {
                __nv_bfloat16 h = __float2bfloat16(vv[j]);
                __nv_bfloat16 l = __float2bfloat16(vv[j] - __bfloat162float(h));
                int bidx = (n4 + j) * (2 * SROW) + kk;
                pH[bidx] = h;
                pL[bidx] = l;
            }
        }
        __syncthreads();

#pragma unroll
        for (int st = 0; st < 2; st++) {
            int k2 = st * 8 + (lane & 3);
            uint32_t a[NI][4];
#pragma unroll
            for (int p = 0; p < 3; p++) {
                const uint32_t* pA = sAb + ((p == 2) ? MT * SROW : 0);
                const uint32_t* pB = sBb + ((p == 1) ? 128 * SROW : 0);
                if (p != 1) {
#pragma unroll
                    for (int i = 0; i < NI; i++) {
                        int r = wm * (MT / 2) + i * 16 + (lane >> 2);
                        a[i][0] = pA[r * SROW + k2];
                        a[i][1] = pA[(r + 8) * SROW + k2];
                        a[i][2] = pA[r * SROW + k2 + 4];
                        a[i][3] = pA[(r + 8) * SROW + k2 + 4];
                    }
                }
#pragma unroll
                for (int j = 0; j < 4; j++) {
                    int c = wn * 32 + j * 8 + (lane >> 2);
                    uint32_t b0 = pB[c * SROW + k2];
                    uint32_t b1 = pB[c * SROW + k2 + 4];
#pragma unroll
                    for (int i = 0; i < NI; i++)
                        mma_bf16(acc[i][j], a[i][0], a[i][1], a[i][2], a[i][3], b0, b1);
                }
            }
        }
    }

    // epilogue: fp32 C + bf16 hi/lo planes (scatter via rowidx)
#pragma unroll
    for (int i = 0; i < NI; i++) {
        int lr0 = wm * (MT / 2) + i * 16 + (lane >> 2);
#pragma unroll
        for (int j = 0; j < 4; j++) {
            int cc = n0 + wn * 32 + j * 8 + (lane & 3) * 2;
#pragma unroll
            for (int hrow = 0; hrow < 2; hrow++) {
                int rr = rowidx[lr0 + hrow * 8];
                if (rr < 0) continue;
                float vx = acc[i][j][hrow * 2 + 0];
                float vy = acc[i][j][hrow * 2 + 1];
                *reinterpret_cast<float2*>(C + (long)rr * ldc + cc) = make_float2(vx, vy);
                uint32_t pl, ph = pack_split(vx, vy, pl);
                reinterpret_cast<uint32_t*>(Ch)[((long)rr * ldc + cc) >> 1] = ph;
                reinterpret_cast<uint32_t*>(Cl)[((long)rr * ldc + cc) >> 1] = pl;
            }
        }
    }
}

// ---------------- 32x128x128 SIMT tile (prep GEMMs) ----------------
__device__ __forceinline__ void gemm32(const float* __restrict__ A,
                                       const float* __restrict__ B,
                                       float* __restrict__ Cf32,
                                       float alpha, int transB,
                                       __nv_bfloat16* oh, __nv_bfloat16* ol,
                                       int o_ld, int rowbase, int colbase)
{
    __shared__ float As[32][33];
    __shared__ float Bs[32][128];
    int tid = threadIdx.x, tx = tid & 15, ty = tid >> 4;
    float acc[2][8];
#pragma unroll
    for (int i = 0; i < 2; i++)
#pragma unroll
        for (int j = 0; j < 8; j++) acc[i][j] = 0.f;

    for (int kt = 0; kt < 128; kt += 32) {
#pragma unroll
        for (int j = 0; j < 4; j++) {
            int lin = tid + j * 256;
            int lr = lin >> 5, lc = lin & 31;
            As[lr][lc] = A[lr * 128 + kt + lc];
        }
#pragma unroll
        for (int j = 0; j < 16; j++) {
            int lin = tid + j * 256;
            int br = lin >> 7, bc = lin & 127;
            Bs[br][bc] = transB ? B[bc * 128 + kt + br] : B[(kt + br) * 128 + bc];
        }
        __syncthreads();
#pragma unroll
        for (int kk = 0; kk < 32; kk++) {
            float bv[8];
#pragma unroll
            for (int j = 0; j < 8; j++) bv[j] = Bs[kk][tx + 16 * j];
#pragma unroll
            for (int i = 0; i < 2; i++) {
                float av = As[ty * 2 + i][kk];
#pragma unroll
                for (int j = 0; j < 8; j++) acc[i][j] += av * bv[j];
            }
        }
        __syncthreads();
    }
    if (Cf32) {
#pragma unroll
        for (int i = 0; i < 2; i++)
#pragma unroll
            for (int j = 0; j < 8; j++)
                Cf32[(ty * 2 + i) * 128 + tx + 16 * j] = acc[i][j] * alpha;
    } else {
#pragma unroll
        for (int i = 0; i < 2; i++) {
            int gr = rowbase + ty * 2 + i;
#pragma unroll
            for (int j = 0; j < 8; j++) {
                int gc = colbase + tx + 16 * j;
                float v = acc[i][j] * alpha;
                __nv_bfloat16 h = __float2bfloat16(v);
                oh[(long)gc * o_ld + gr] = h;
                ol[(long)gc * o_ld + gr] = __float2bfloat16(v - __bfloat162float(h));
            }
        }
    }
}

// prep_fused: phase1 (T/S) -> global barrier -> phase2 (BkT/BvT planes). 64 blocks.
__global__ __launch_bounds__(256) void prep_fused(const float* __restrict__ rel_w,
                                                  const float* __restrict__ k_w,
                                                  const float* __restrict__ v_w,
                                                  const float* __restrict__ q_w,
                                                  const float* __restrict__ fc_w)
{
    int b = blockIdx.x;
    int j = b >> 2, sub = b & 3;
    int tid = threadIdx.x;

    if (b == 0 && tid < ENTT) g_cnt[tid] = 0;   // consumed by partition_kernel (next launch)

    {   // phase 1
        int r = j & 7, ph = j >> 3;
        const float* A = rel_w + r * (UU * UU) + sub * 32 * UU;
        const float* B = ph ? v_w : k_w;
        float* C = (ph ? g_S : g_T) + r * (UU * UU) + sub * 32 * UU;
        gemm32(A, B, C, 1.f, 0, nullptr, nullptr, 0, 0, 0);
    }

    // global barrier (monotone ticket: 64 arrivals per replay, no reset needed)
    __syncthreads();
    if (tid == 0) {
        __threadfence();
        int ticket = atomicAdd(&g_bar, 1);
        int target = ((ticket >> 6) + 1) << 6;
        while (atomicAdd(&g_bar, 0) < target) __nanosleep(64);
        __threadfence();
    }
    __syncthreads();

    {   // phase 2
        if (j < 8) {
            int r = j;
            gemm32(q_w + sub * 32 * UU, g_T + r * (UU * UU), nullptr,
                   1.f / 128.f, 1, g_BkTh, g_BkTl, 128, sub * 32, r * UU);
        } else {
            int r = j - 8;
            gemm32(g_S + r * (UU * UU) + sub * 32 * UU, fc_w, nullptr,
                   1.f, 0, g_BvTh, g_BvTl, 1024, r * UU + sub * 32, 0);
        }
    }
}

// ---------------- entity partition ----------------
__global__ void partition_kernel(const int* __restrict__ pe) {
    int n = blockIdx.x * blockDim.x + threadIdx.x;
    if (n < NN) {
        int e = pe[n];
        int pos = atomicAdd(&g_cnt[e], 1);
        g_lists[e * NN + pos] = n;
    }
}

// ---------------- fused gather / score / softmax / weighted-scatter ----------------
__global__ __launch_bounds__(128) void edge_kernel(const int* __restrict__ adjacency,
                                                   const int* __restrict__ relation)
{
    __shared__ float xs[DD][UU];
    __shared__ float aw[RR][DD];
    __shared__ float scores[DD];
    __shared__ int adjs[DD];
    __shared__ int rels[DD];

    int n = blockIdx.x;
    int tid = threadIdx.x, lane = tid & 31, w = tid >> 5;

    if (tid < DD) {
        adjs[tid] = adjacency[n * DD + tid];
        rels[tid] = relation[n * DD + tid];
    }
    __syncthreads();

#pragma unroll
    for (int i = 0; i < 8; i++) {
        int d = w * 8 + i;
        int idx = adjs[d];
        float4 v = (idx > 0)
            ? reinterpret_cast<const float4*>(g_center + (idx - 1) * UU)[lane]
            : make_float4(0.f, 0.f, 0.f, 0.f);
        reinterpret_cast<float4*>(&xs[d][0])[lane] = v;
    }
    __syncwarp();

    const float* qbase = g_qr + n * (RR * UU);
#pragma unroll
    for (int i = 0; i < 8; i++) {
        int d = w * 8 + i;
        int r = rels[d];
        const float* q = qbase + r * UU;
        float s = 0.f;
#pragma unroll
        for (int k2 = 0; k2 < 4; k2++) {
            int c = lane + 32 * k2;
            s += q[c] * xs[d][c];
        }
#pragma unroll
        for (int off = 16; off > 0; off >>= 1) s += __shfl_xor_sync(0xffffffffu, s, off);
        if (lane == 0) scores[d] = (r == 0) ? -1e9f : s;
    }
    __syncthreads();

    if (w == 0) {
        float v = scores[lane];
        float m = v;
#pragma unroll
        for (int off = 16; off > 0; off >>= 1) m = fmaxf(m, __shfl_xor_sync(0xffffffffu, m, off));
        float e = __expf(v - m);
        float sum = e;
#pragma unroll
        for (int off = 16; off > 0; off >>= 1) sum += __shfl_xor_sync(0xffffffffu, sum, off);
        float a = e / sum;
        int r = rels[lane];
#pragma unroll
        for (int rr = 0; rr < RR; rr++) aw[rr][lane] = (r == rr) ? a : 0.f;
    }
    __syncthreads();

    float acc[RR];
#pragma unroll
    for (int r = 0; r < RR; r++) acc[r] = 0.f;
#pragma unroll
    for (int d = 0; d < DD; d++) {
        float x = xs[d][tid];
#pragma unroll
        for (int r = 0; r < RR; r++) acc[r] += aw[r][d] * x;
    }
    __nv_bfloat16* sph = g_sh + (long)n * (RR * UU) + tid;
    __nv_bfloat16* spl = g_sl + (long)n * (RR * UU) + tid;
#pragma unroll
    for (int r = 0; r < RR; r++) {
        float v = acc[r];
        __nv_bfloat16 h = __float2bfloat16(v);
        sph[r * UU] = h;
        spl[r * UU] = __float2bfloat16(v - __bfloat162float(h));
    }
}

// ---------------- launch ----------------
extern "C" void kernel_launch(void* const* d_in, const int* in_sizes, int n_in,
                              void* d_out, int out_size)
{
    const float* node_state = (const float*)d_in[0];
    const int*   adjacency  = (const int*)d_in[1];
    const int*   point_enc  = (const int*)d_in[2];
    const int*   relation   = (const int*)d_in[3];
    const float* pe_w       = (const float*)d_in[4];
    const float* rel_w      = (const float*)d_in[5];
    const float* q_w        = (const float*)d_in[6];
    const float* k_w        = (const float*)d_in[7];
    const float* v_w        = (const float*)d_in[8];
    const float* fc_w       = (const float*)d_in[9];
    const float* fc_b       = (const float*)d_in[10];
    float* out = (float*)d_out;

    float *p_center, *p_qr;
    __nv_bfloat16 *p_ch, *p_cl, *p_sh, *p_sl, *p_bkh, *p_bkl, *p_bvh, *p_bvl;
    int *p_cnt, *p_lists;
    cudaGetSymbolAddress((void**)&p_center, g_center);
    cudaGetSymbolAddress((void**)&p_qr,     g_qr);
    cudaGetSymbolAddress((void**)&p_ch,     g_center_h);
    cudaGetSymbolAddress((void**)&p_cl,     g_center_l);
    cudaGetSymbolAddress((void**)&p_sh,     g_sh);
    cudaGetSymbolAddress((void**)&p_sl,     g_sl);
    cudaGetSymbolAddress((void**)&p_bkh,    g_BkTh);
    cudaGetSymbolAddress((void**)&p_bkl,    g_BkTl);
    cudaGetSymbolAddress((void**)&p_bvh,    g_BvTh);
    cudaGetSymbolAddress((void**)&p_bvl,    g_BvTl);
    cudaGetSymbolAddress((void**)&p_cnt,    g_cnt);
    cudaGetSymbolAddress((void**)&p_lists,  g_lists);

    cudaFuncSetAttribute(mma_gemm_f32, cudaFuncAttributeMaxDynamicSharedMemorySize, SMEM_MMA);
    cudaFuncSetAttribute(mma_pre<128>, cudaFuncAttributeMaxDynamicSharedMemorySize, SMEM_PRE(128));
    cudaFuncSetAttribute(mma_pre<64>,  cudaFuncAttributeMaxDynamicSharedMemorySize, SMEM_PRE(64));

    // 1. prep: g_cnt zero + T/S -> (barrier) -> BkT/BvT planes (one fused launch)
    prep_fused<<<64, 256>>>(rel_w, k_w, v_w, q_w, fc_w);
    // 2. entity partition
    partition_kernel<<<NN / 256, 256>>>(point_enc);

    // 3. center = gathered GEMM (fp32 in); emits fp32 + bf16 hi/lo planes
    mma_gemm_f32<<<dim3(32, 1, 8), 256, SMEM_MMA>>>(
        node_state, INPD, pe_w, 128, (long)INPD * UU,
        p_center, 128, INPD,
        p_lists, p_cnt, p_ch, p_cl);

    // 4. qr = center @ Bk2   (N x 1024, K=128) — ldmatrix + B-reuse
    mma_pre<128><<<dim3(128, 8), 256, SMEM_PRE(128)>>>(
        p_ch, p_cl, p_bkh, p_bkl, 128,
        p_qr, 1024, nullptr, nullptr, 0);

    // 5. fused gather / scores / softmax / per-relation weighted sums -> s planes
    edge_kernel<<<NN, 128>>>(adjacency, relation);

    // 6. out = center + relu(s @ Bv2 + fc_b)   (N x 128, K=1024)
    mma_pre<64><<<dim3(256, 1), 256, SMEM_PRE(64)>>>(
        p_sh, p_sl, p_bvh, p_bvl, 1024,
        out, 128, fc_b, p_center, 1);
}

// round 14
// speedup vs baseline: 1.2720x; 1.1168x over previous
#include <cuda_runtime.h>
#include <cuda_bf16.h>
#include <cuda_fp16.h>
#include <cstdint>

#define NN  16384
#define DD  32
#define INPD 256
#define UU  128
#define RR  8
#define ENTT 8

// ---------------- scratch (device globals: no allocation allowed) ----------------
__device__ float g_center[NN * UU];            // (N, U) fp32
__device__ __half g_center_h[NN * UU];         // center hi plane (fp16)
__device__ __half g_center_l[NN * UU];         // center lo plane (fp16)
__device__ float g_qr[NN * RR * UU];           // (N, R*U) fp32
__device__ __half g_sh[NN * RR * UU];          // s hi plane (fp16)
__device__ __half g_sl[NN * RR * UU];          // s lo plane (fp16)
__device__ float g_T[RR * UU * UU];            // T[r] = rel[r] @ k_w
__device__ float g_S[RR * UU * UU];            // S[r] = rel[r] @ v_w
__device__ __half g_BkT[RR * UU * UU];         // Bk2^T fp16: [1024][128]
__device__ __half g_BvT[RR * UU * UU];         // Bv2^T fp16: [128][1024]
__device__ int   g_cnt[ENTT];
__device__ int   g_lists[ENTT * NN];
__device__ int   g_bar;                         // monotone barrier ticket

// ======================= warp-level MMA (HMMA path, plain sm_103) =======================
__device__ __forceinline__ void mma_bf16(float* d,
                                         uint32_t a0, uint32_t a1, uint32_t a2, uint32_t a3,
                                         uint32_t b0, uint32_t b1)
{
    asm volatile(
        "mma.sync.aligned.m16n8k16.row.col.f32.bf16.bf16.f32 "
        "{%0,%1,%2,%3}, {%4,%5,%6,%7}, {%8,%9}, {%0,%1,%2,%3};"
        : "+f"(d[0]), "+f"(d[1]), "+f"(d[2]), "+f"(d[3])
        : "r"(a0), "r"(a1), "r"(a2), "r"(a3), "r"(b0), "r"(b1));
}
__device__ __forceinline__ void mma_f16(float* d,
                                        uint32_t a0, uint32_t a1, uint32_t a2, uint32_t a3,
                                        uint32_t b0, uint32_t b1)
{
    asm volatile(
        "mma.sync.aligned.m16n8k16.row.col.f32.f16.f16.f32 "
        "{%0,%1,%2,%3}, {%4,%5,%6,%7}, {%8,%9}, {%0,%1,%2,%3};"
        : "+f"(d[0]), "+f"(d[1]), "+f"(d[2]), "+f"(d[3])
        : "r"(a0), "r"(a1), "r"(a2), "r"(a3), "r"(b0), "r"(b1));
}

__device__ __forceinline__ void ldm_x4(uint32_t& r0, uint32_t& r1, uint32_t& r2, uint32_t& r3,
                                       uint32_t addr)
{
    asm volatile("ldmatrix.sync.aligned.m8n8.x4.shared.b16 {%0,%1,%2,%3}, [%4];"
                 : "=r"(r0), "=r"(r1), "=r"(r2), "=r"(r3) : "r"(addr));
}

__device__ __forceinline__ void cp16(uint32_t dst, const void* src, int sz) {
    asm volatile("cp.async.ca.shared.global [%0], [%1], 16, %2;"
                 :: "r"(dst), "l"(src), "r"(sz) : "memory");
}
#define CP_COMMIT() asm volatile("cp.async.commit_group;" ::: "memory")
#define CP_WAIT1()  asm volatile("cp.async.wait_group 1;" ::: "memory")
#define CP_WAIT0()  asm volatile("cp.async.wait_group 0;" ::: "memory")

// XOR swizzle at 16B-chunk granularity (rows are 16 words of packed 16-bit pairs).
__device__ __forceinline__ int swz(int row, int c) {
    return row * 16 + ((c ^ (row & 3) ^ ((row >> 2) & 1)) << 2);
}

__device__ __forceinline__ uint32_t pack_split_bf(float x, float y, uint32_t& lo) {
    __nv_bfloat16 hx = __float2bfloat16(x), hy = __float2bfloat16(y);
    __nv_bfloat16 lx = __float2bfloat16(x - __bfloat162float(hx));
    __nv_bfloat16 ly = __float2bfloat16(y - __bfloat162float(hy));
    lo = ((uint32_t)__bfloat16_as_ushort(ly) << 16) | __bfloat16_as_ushort(lx);
    return ((uint32_t)__bfloat16_as_ushort(hy) << 16) | __bfloat16_as_ushort(hx);
}
__device__ __forceinline__ uint32_t pack_split_h(float x, float y, uint32_t& lo) {
    __half hx = __float2half_rn(x), hy = __float2half_rn(y);
    __half lx = __float2half_rn(x - __half2float(hx));
    __half ly = __float2half_rn(y - __half2float(hy));
    lo = ((uint32_t)__half_as_ushort(ly) << 16) | __half_as_ushort(lx);
    return ((uint32_t)__half_as_ushort(hy) << 16) | __half_as_ushort(hx);
}

// ======================= fp16 2-pass GEMM (3-stage cp.async + ldmatrix) ====================
// C[MT x 128] = (Ah+Al) @ B^T ; A hi/lo fp16 planes [M][K], BT single fp16 plane [N][K].
#define STGW(MT) (2*(MT)*16 + 128*16)
#define SMEM_PRE(MT) (3 * STGW(MT) * 4)

template<int MT>
__device__ __forceinline__ void issue_chunk(
    uint32_t stg_base, int kc,
    const __half* Ah, const __half* Al, const __half* B,
    int K, int m0, int n0, int tid)
{
#pragma unroll
    for (int it = 0; it < MT / 64; it++) {
        int lin = tid + it * 256;
        int row = lin >> 2, c = lin & 3;
        int wd = swz(row, c);
        long off = (long)(m0 + row) * K + kc * 32 + c * 8;
        cp16(stg_base + wd * 4, Ah + off, 16);
        cp16(stg_base + (MT * 16 + wd) * 4, Al + off, 16);
    }
#pragma unroll
    for (int it = 0; it < 2; it++) {
        int lin = tid + it * 256;
        int row = lin >> 2, c = lin & 3;
        int wd = swz(row, c);
        long off = (long)(n0 + row) * K + kc * 32 + c * 8;
        cp16(stg_base + (2 * MT * 16 + wd) * 4, B + off, 16);
    }
}

template<int MT>
__global__ __launch_bounds__(256, 2) void mma_pre(
    const __half* __restrict__ Ah, const __half* __restrict__ Al,
    const __half* __restrict__ B,
    int K,
    float* __restrict__ C, int ldc,
    const float* __restrict__ bias, const float* __restrict__ addsrc, int do_relu)
{
    constexpr int NI = MT / 32;
    extern __shared__ char smem[];
    uint32_t sb0 = (uint32_t)__cvta_generic_to_shared(smem);

    const int tid  = threadIdx.x;
    const int lane = tid & 31;
    const int w    = tid >> 5;
    const int wm   = w >> 2;
    const int wn   = w & 3;
    const int q    = lane >> 2;
    const int s4   = lane & 3;
    const int lrow = lane & 7;
    const int seg  = lane >> 3;
    const int m0   = blockIdx.x * MT;
    const int n0   = blockIdx.y * 128;

    float acc[NI][4][4];
#pragma unroll
    for (int i = 0; i < NI; i++)
#pragma unroll
        for (int j = 0; j < 4; j++)
#pragma unroll
            for (int r = 0; r < 4; r++) acc[i][j][r] = 0.f;

    const int nk = K / 32;
    issue_chunk<MT>(sb0, 0, Ah, Al, B, K, m0, n0, tid);
    CP_COMMIT();
    issue_chunk<MT>(sb0 + STGW(MT) * 4, 1, Ah, Al, B, K, m0, n0, tid);
    CP_COMMIT();

    for (int kt = 0; kt < nk; kt++) {
        CP_WAIT1();
        __syncthreads();

        const uint32_t stg = sb0 + (kt % 3) * STGW(MT) * 4;
        const uint32_t oAh = stg;
        const uint32_t oAl = stg + MT * 16 * 4;
        const uint32_t oB  = stg + 2 * MT * 16 * 4;

#pragma unroll
        for (int st = 0; st < 2; st++) {
            const int c0 = st * 2;
            const int achk = c0 + (seg >> 1);
            const int aoff = lrow + (seg & 1) * 8;
            const int bchk = c0 + (seg & 1);
            const int bsel = (seg >> 1);

            uint32_t aR[NI][4], bR[4][2];

            // --- load B (single plane) ---
#pragma unroll
            for (int jp = 0; jp < 2; jp++) {
                int bcol = wn * 32 + (jp * 2 + bsel) * 8 + lrow;
                ldm_x4(bR[jp * 2][0], bR[jp * 2][1], bR[jp * 2 + 1][0], bR[jp * 2 + 1][1],
                       oB + swz(bcol, bchk) * 4);
            }
            // --- pass 0: Ah * B ---
#pragma unroll
            for (int i = 0; i < NI; i++) {
                int arow = wm * (MT / 2) + i * 16 + aoff;
                ldm_x4(aR[i][0], aR[i][1], aR[i][2], aR[i][3], oAh + swz(arow, achk) * 4);
            }
#pragma unroll
            for (int j = 0; j < 4; j++)
#pragma unroll
                for (int i = 0; i < NI; i++)
                    mma_f16(acc[i][j], aR[i][0], aR[i][1], aR[i][2], aR[i][3],
                            bR[j][0], bR[j][1]);
            // --- pass 1: Al * B ---
#pragma unroll
            for (int i = 0; i < NI; i++) {
                int arow = wm * (MT / 2) + i * 16 + aoff;
                ldm_x4(aR[i][0], aR[i][1], aR[i][2], aR[i][3], oAl + swz(arow, achk) * 4);
            }
#pragma unroll
            for (int j = 0; j < 4; j++)
#pragma unroll
                for (int i = 0; i < NI; i++)
                    mma_f16(acc[i][j], aR[i][0], aR[i][1], aR[i][2], aR[i][3],
                            bR[j][0], bR[j][1]);
        }
        if (kt + 2 < nk)
            issue_chunk<MT>(sb0 + ((kt + 2) % 3) * STGW(MT) * 4, kt + 2,
                            Ah, Al, B, K, m0, n0, tid);
        CP_COMMIT();
    }

    // ---- epilogue ----
#pragma unroll
    for (int i = 0; i < NI; i++) {
        int r0 = m0 + wm * (MT / 2) + i * 16 + q;
#pragma unroll
        for (int j = 0; j < 4; j++) {
            int cc = n0 + wn * 32 + j * 8 + s4 * 2;
            float bx = 0.f, by = 0.f;
            if (bias) { bx = bias[cc]; by = bias[cc + 1]; }
#pragma unroll
            for (int hrow = 0; hrow < 2; hrow++) {
                int rr = r0 + hrow * 8;
                float vx = acc[i][j][hrow * 2 + 0] + bx;
                float vy = acc[i][j][hrow * 2 + 1] + by;
                if (do_relu) { vx = fmaxf(vx, 0.f); vy = fmaxf(vy, 0.f); }
                if (addsrc) {
                    const float2 av = *reinterpret_cast<const float2*>(addsrc + (long)rr * ldc + cc);
                    vx += av.x; vy += av.y;
                }
                *reinterpret_cast<float2*>(C + (long)rr * ldc + cc) = make_float2(vx, vy);
            }
        }
    }
}

// ======================= fp32-input pipelined MMA (center: gather + 3-pass bf16) =============
#define SROW 17
#define SMEM_MMA (512 + 128*256 + 32768 + 2*128*SROW*4 + 2*128*SROW*4)

__global__ __launch_bounds__(256) void mma_gemm_f32(
    const float* __restrict__ A, int lda,
    const float* __restrict__ B, int ldb, long sBz,
    float* __restrict__ C, int ldc, int K,
    const int* __restrict__ rowlists, const int* __restrict__ cnts,
    __half* __restrict__ Ch, __half* __restrict__ Cl)
{
    constexpr int MT = 128;
    constexpr int NI = 4;
    extern __shared__ char smem[];
    int*      rowidx = (int*)smem;
    float*    rawA   = (float*)(smem + 512);
    float*    rawB   = (float*)(smem + 512 + MT * 256);
    uint32_t* sAb    = (uint32_t*)(smem + 512 + MT * 256 + 32768);
    uint32_t* sBb    = sAb + 2 * MT * SROW;

    const int tid  = threadIdx.x;
    const int lane = tid & 31;
    const int w    = tid >> 5;
    const int wm   = w >> 2;
    const int wn   = w & 3;
    const int m0   = blockIdx.x * MT;
    const int n0   = blockIdx.y * 128;
    const int z    = blockIdx.z;

    int rows = cnts[z];
    if (m0 >= rows) return;
    const int* rl = rowlists + z * NN;
    B += z * sBz;

    if (tid < MT) {
        int g = m0 + tid;
        rowidx[tid] = (g < rows) ? rl[g] : -1;
    }
    __syncthreads();

    float acc[NI][4][4];
#pragma unroll
    for (int i = 0; i < NI; i++)
#pragma unroll
        for (int j = 0; j < 4; j++)
#pragma unroll
            for (int r = 0; r < 4; r++) acc[i][j][r] = 0.f;

    const int nk = K / 32;
    {
#pragma unroll
        for (int it = 0; it < NI; it++) {
            int lin = tid + it * 256;
            int row = lin >> 3, f4 = lin & 7;
            int ar = rowidx[row];
            const float* src = (ar >= 0) ? (A + (long)ar * lda + f4 * 4) : A;
            cp16((uint32_t)__cvta_generic_to_shared(rawA + row * 32 + f4 * 4), src,
                 (ar >= 0) ? 16 : 0);
        }
#pragma unroll
        for (int it = 0; it < 4; it++) {
            int lin = tid + it * 256;
            int kk = lin >> 5, n4 = (lin & 31) * 4;
            cp16((uint32_t)__cvta_generic_to_shared(rawB + kk * 128 + n4),
                 B + (long)kk * ldb + n0 + n4, 16);
        }
        CP_COMMIT();
    }

    for (int kt = 0; kt < nk; kt++) {
        const int cur = kt & 1;
        if (kt + 1 < nk) {
            const int nxt = cur ^ 1;
            const int k0 = (kt + 1) * 32;
#pragma unroll
            for (int it = 0; it < NI; it++) {
                int lin = tid + it * 256;
                int row = lin >> 3, f4 = lin & 7;
                int ar = rowidx[row];
                const float* src = (ar >= 0) ? (A + (long)ar * lda + k0 + f4 * 4) : A;
                cp16((uint32_t)__cvta_generic_to_shared(rawA + nxt * MT * 32 + row * 32 + f4 * 4),
                     src, (ar >= 0) ? 16 : 0);
            }
#pragma unroll
            for (int it = 0; it < 4; it++) {
                int lin = tid + it * 256;
                int kk = lin >> 5, n4 = (lin & 31) * 4;
                cp16((uint32_t)__cvta_generic_to_shared(rawB + nxt * 4096 + kk * 128 + n4),
                     B + (long)(k0 + kk) * ldb + n0 + n4, 16);
            }
            CP_COMMIT();
            CP_WAIT1();
        } else {
            CP_WAIT0();
        }
        __syncthreads();

        const float* rA = rawA + cur * MT * 32;
#pragma unroll
        for (int it = 0; it < NI; it++) {
            int lin = tid + it * 256;
            int row = lin >> 3, f4 = lin & 7;
            float4 v = *reinterpret_cast<const float4*>(rA + row * 32 + f4 * 4);
            uint32_t l0, l1;
            uint32_t h0 = pack_split_bf(v.x, v.y, l0);
            uint32_t h1 = pack_split_bf(v.z, v.w, l1);
            int idx = row * SROW + f4 * 2;
            sAb[idx]                 = h0;
            sAb[idx + 1]             = h1;
            sAb[MT * SROW + idx]     = l0;
            sAb[MT * SROW + idx + 1] = l1;
        }
        const float* rB = rawB + cur * 4096;
#pragma unroll
        for (int it = 0; it < 4; it++) {
            int lin = tid + it * 256;
            int kk = lin >> 5, n4 = (lin & 31) * 4;
            float4 v = *reinterpret_cast<const float4*>(rB + kk * 128 + n4);
            float vv[4] = {v.x, v.y, v.z, v.w};
            __nv_bfloat16* pH = reinterpret_cast<__nv_bfloat16*>(sBb);
            __nv_bfloat16* pL = reinterpret_cast<__nv_bfloat16*>(sBb + 128 * SROW);
#pragma unroll
            for (int j = 0; j < 4; j++) {
                __nv_bfloat16 h = __float2bfloat16(vv[j]);
                __nv_bfloat16 l = __float2bfloat16(vv[j] - __bfloat162float(h));
                int bidx = (n4 + j) * (2 * SROW) + kk;
                pH[bidx] = h;
                pL[bidx] = l;
            }
        }
        __syncthreads();

#pragma unroll
        for (int st = 0; st < 2; st++) {
            int k2 = st * 8 + (lane & 3);
            uint32_t a[NI][4];
#pragma unroll
            for (int p = 0; p < 3; p++) {
                const uint32_t* pA = sAb + ((p == 2) ? MT * SROW : 0);
                const uint32_t* pB = sBb + ((p == 1) ? 128 * SROW : 0);
                if (p != 1) {
#pragma unroll
                    for (int i = 0; i < NI; i++) {
                        int r = wm * (MT / 2) + i * 16 + (lane >> 2);
                        a[i][0] = pA[r * SROW + k2];
                        a[i][1] = pA[(r + 8) * SROW + k2];
                        a[i][2] = pA[r * SROW + k2 + 4];
                        a[i][3] = pA[(r + 8) * SROW + k2 + 4];
                    }
                }
#pragma unroll
                for (int j = 0; j < 4; j++) {
                    int c = wn * 32 + j * 8 + (lane >> 2);
                    uint32_t b0 = pB[c * SROW + k2];
                    uint32_t b1 = pB[c * SROW + k2 + 4];
#pragma unroll
                    for (int i = 0; i < NI; i++)
                        mma_bf16(acc[i][j], a[i][0], a[i][1], a[i][2], a[i][3], b0, b1);
                }
            }
        }
    }

    // epilogue: fp32 C + fp16 hi/lo planes (scatter via rowidx)
#pragma unroll
    for (int i = 0; i < NI; i++) {
        int lr0 = wm * (MT / 2) + i * 16 + (lane >> 2);
#pragma unroll
        for (int j = 0; j < 4; j++) {
            int cc = n0 + wn * 32 + j * 8 + (lane & 3) * 2;
#pragma unroll
            for (int hrow = 0; hrow < 2; hrow++) {
                int rr = rowidx[lr0 + hrow * 8];
                if (rr < 0) continue;
                float vx = acc[i][j][hrow * 2 + 0];
                float vy = acc[i][j][hrow * 2 + 1];
                *reinterpret_cast<float2*>(C + (long)rr * ldc + cc) = make_float2(vx, vy);
                uint32_t pl, ph = pack_split_h(vx, vy, pl);
                reinterpret_cast<uint32_t*>(Ch)[((long)rr * ldc + cc) >> 1] = ph;
                reinterpret_cast<uint32_t*>(Cl)[((long)rr * ldc + cc) >> 1] = pl;
            }
        }
    }
}

// ---------------- 32x128x128 SIMT tile (prep GEMMs) ----------------
// If Cf32: write fp32. Else: write transposed single fp16 plane oh.
__device__ __forceinline__ void gemm32(const float* __restrict__ A,
                                       const float* __restrict__ B,
                                       float* __restrict__ Cf32,
                                       float alpha, int transB,
                                       __half* oh, int o_ld, int rowbase, int colbase)
{
    __shared__ float As[32][33];
    __shared__ float Bs[32][128];
    int tid = threadIdx.x, tx = tid & 15, ty = tid >> 4;
    float acc[2][8];
#pragma unroll
    for (int i = 0; i < 2; i++)
#pragma unroll
        for (int j = 0; j < 8; j++) acc[i][j] = 0.f;

    for (int kt = 0; kt < 128; kt += 32) {
#pragma unroll
        for (int j = 0; j < 4; j++) {
            int lin = tid + j * 256;
            int lr = lin >> 5, lc = lin & 31;
            As[lr][lc] = A[lr * 128 + kt + lc];
        }
#pragma unroll
        for (int j = 0; j < 16; j++) {
            int lin = tid + j * 256;
            int br = lin >> 7, bc = lin & 127;
            Bs[br][bc] = transB ? B[bc * 128 + kt + br] : B[(kt + br) * 128 + bc];
        }
        __syncthreads();
#pragma unroll
        for (int kk = 0; kk < 32; kk++) {
            float bv[8];
#pragma unroll
            for (int j = 0; j < 8; j++) bv[j] = Bs[kk][tx + 16 * j];
#pragma unroll
            for (int i = 0; i < 2; i++) {
                float av = As[ty * 2 + i][kk];
#pragma unroll
                for (int j = 0; j < 8; j++) acc[i][j] += av * bv[j];
            }
        }
        __syncthreads();
    }
    if (Cf32) {
#pragma unroll
        for (int i = 0; i < 2; i++)
#pragma unroll
            for (int j = 0; j < 8; j++)
                Cf32[(ty * 2 + i) * 128 + tx + 16 * j] = acc[i][j] * alpha;
    } else {
#pragma unroll
        for (int i = 0; i < 2; i++) {
            int gr = rowbase + ty * 2 + i;
#pragma unroll
            for (int j = 0; j < 8; j++) {
                int gc = colbase + tx + 16 * j;
                oh[(long)gc * o_ld + gr] = __float2half_rn(acc[i][j] * alpha);
            }
        }
    }
}

// prep_fused: phase1 (T/S) -> global barrier -> phase2 (BkT/BvT fp16 planes). 64 blocks.
__global__ __launch_bounds__(256) void prep_fused(const float* __restrict__ rel_w,
                                                  const float* __restrict__ k_w,
                                                  const float* __restrict__ v_w,
                                                  const float* __restrict__ q_w,
                                                  const float* __restrict__ fc_w)
{
    int b = blockIdx.x;
    int j = b >> 2, sub = b & 3;
    int tid = threadIdx.x;

    if (b == 0 && tid < ENTT) g_cnt[tid] = 0;   // consumed by partition_kernel (next launch)

    {   // phase 1
        int r = j & 7, ph = j >> 3;
        const float* A = rel_w + r * (UU * UU) + sub * 32 * UU;
        const float* B = ph ? v_w : k_w;
        float* C = (ph ? g_S : g_T) + r * (UU * UU) + sub * 32 * UU;
        gemm32(A, B, C, 1.f, 0, nullptr, 0, 0, 0);
    }

    // global barrier (monotone ticket: 64 arrivals per replay, no reset needed)
    __syncthreads();
    if (tid == 0) {
        __threadfence();
        int ticket = atomicAdd(&g_bar, 1);
        int target = ((ticket >> 6) + 1) << 6;
        while (atomicAdd(&g_bar, 0) < target) __nanosleep(64);
        __threadfence();
    }
    __syncthreads();

    {   // phase 2
        if (j < 8) {
            int r = j;
            gemm32(q_w + sub * 32 * UU, g_T + r * (UU * UU), nullptr,
                   1.f / 128.f, 1, g_BkT, 128, sub * 32, r * UU);
        } else {
            int r = j - 8;
            gemm32(g_S + r * (UU * UU) + sub * 32 * UU, fc_w, nullptr,
                   1.f, 0, g_BvT, 1024, r * UU + sub * 32, 0);
        }
    }
}

// ---------------- entity partition ----------------
__global__ void partition_kernel(const int* __restrict__ pe) {
    int n = blockIdx.x * blockDim.x + threadIdx.x;
    if (n < NN) {
        int e = pe[n];
        int pos = atomicAdd(&g_cnt[e], 1);
        g_lists[e * NN + pos] = n;
    }
}

// ---------------- fused gather / score / softmax / weighted-scatter ----------------
__global__ __launch_bounds__(128) void edge_kernel(const int* __restrict__ adjacency,
                                                   const int* __restrict__ relation)
{
    __shared__ float xs[DD][UU];
    __shared__ float aw[RR][DD];
    __shared__ float scores[DD];
    __shared__ int adjs[DD];
    __shared__ int rels[DD];

    int n = blockIdx.x;
    int tid = threadIdx.x, lane = tid & 31, w = tid >> 5;

    if (tid < DD) {
        adjs[tid] = adjacency[n * DD + tid];
        rels[tid] = relation[n * DD + tid];
    }
    __syncthreads();

#pragma unroll
    for (int i = 0; i < 8; i++) {
        int d = w * 8 + i;
        int idx = adjs[d];
        float4 v = (idx > 0)
            ? reinterpret_cast<const float4*>(g_center + (idx - 1) * UU)[lane]
            : make_float4(0.f, 0.f, 0.f, 0.f);
        reinterpret_cast<float4*>(&xs[d][0])[lane] = v;
    }
    __syncwarp();

    const float* qbase = g_qr + n * (RR * UU);
#pragma unroll
    for (int i = 0; i < 8; i++) {
        int d = w * 8 + i;
        int r = rels[d];
        const float* q = qbase + r * UU;
        float s = 0.f;
#pragma unroll
        for (int k2 = 0; k2 < 4; k2++) {
            int c = lane + 32 * k2;
            s += q[c] * xs[d][c];
        }
#pragma unroll
        for (int off = 16; off > 0; off >>= 1) s += __shfl_xor_sync(0xffffffffu, s, off);
        if (lane == 0) scores[d] = (r == 0) ? -1e9f : s;
    }
    __syncthreads();

    if (w == 0) {
        float v = scores[lane];
        float m = v;
#pragma unroll
        for (int off = 16; off > 0; off >>= 1) m = fmaxf(m, __shfl_xor_sync(0xffffffffu, m, off));
        float e = __expf(v - m);
        float sum = e;
#pragma unroll
        for (int off = 16; off > 0; off >>= 1) sum += __shfl_xor_sync(0xffffffffu, sum, off);
        float a = e / sum;
        int r = rels[lane];
#pragma unroll
        for (int rr = 0; rr < RR; rr++) aw[rr][lane] = (r == rr) ? a : 0.f;
    }
    __syncthreads();

    float acc[RR];
#pragma unroll
    for (int r = 0; r < RR; r++) acc[r] = 0.f;
#pragma unroll
    for (int d = 0; d < DD; d++) {
        float x = xs[d][tid];
#pragma unroll
        for (int r = 0; r < RR; r++) acc[r] += aw[r][d] * x;
    }
    __half* sph = g_sh + (long)n * (RR * UU) + tid;
    __half* spl = g_sl + (long)n * (RR * UU) + tid;
#pragma unroll
    for (int r = 0; r < RR; r++) {
        float v = acc[r];
        __half h = __float2half_rn(v);
        sph[r * UU] = h;
        spl[r * UU] = __float2half_rn(v - __half2float(h));
    }
}

// ---------------- launch ----------------
extern "C" void kernel_launch(void* const* d_in, const int* in_sizes, int n_in,
                              void* d_out, int out_size)
{
    const float* node_state = (const float*)d_in[0];
    const int*   adjacency  = (const int*)d_in[1];
    const int*   point_enc  = (const int*)d_in[2];
    const int*   relation   = (const int*)d_in[3];
    const float* pe_w       = (const float*)d_in[4];
    const float* rel_w      = (const float*)d_in[5];
    const float* q_w        = (const float*)d_in[6];
    const float* k_w        = (const float*)d_in[7];
    const float* v_w        = (const float*)d_in[8];
    const float* fc_w       = (const float*)d_in[9];
    const float* fc_b       = (const float*)d_in[10];
    float* out = (float*)d_out;

    float *p_center, *p_qr;
    __half *p_ch, *p_cl, *p_sh, *p_sl, *p_bk, *p_bv;
    int *p_cnt, *p_lists;
    cudaGetSymbolAddress((void**)&p_center, g_center);
    cudaGetSymbolAddress((void**)&p_qr,     g_qr);
    cudaGetSymbolAddress((void**)&p_ch,     g_center_h);
    cudaGetSymbolAddress((void**)&p_cl,     g_center_l);
    cudaGetSymbolAddress((void**)&p_sh,     g_sh);
    cudaGetSymbolAddress((void**)&p_sl,     g_sl);
    cudaGetSymbolAddress((void**)&p_bk,     g_BkT);
    cudaGetSymbolAddress((void**)&p_bv,     g_BvT);
    cudaGetSymbolAddress((void**)&p_cnt,    g_cnt);
    cudaGetSymbolAddress((void**)&p_lists,  g_lists);

    cudaFuncSetAttribute(mma_gemm_f32, cudaFuncAttributeMaxDynamicSharedMemorySize, SMEM_MMA);
    cudaFuncSetAttribute(mma_pre<128>, cudaFuncAttributeMaxDynamicSharedMemorySize, SMEM_PRE(128));
    cudaFuncSetAttribute(mma_pre<64>,  cudaFuncAttributeMaxDynamicSharedMemorySize, SMEM_PRE(64));

    // 1. prep: g_cnt zero + T/S -> (barrier) -> BkT/BvT fp16 planes (one fused launch)
    prep_fused<<<64, 256>>>(rel_w, k_w, v_w, q_w, fc_w);
    // 2. entity partition
    partition_kernel<<<NN / 256, 256>>>(point_enc);

    // 3. center = gathered GEMM (fp32 in, 3-pass bf16); emits fp32 + fp16 hi/lo planes
    mma_gemm_f32<<<dim3(32, 1, 8), 256, SMEM_MMA>>>(
        node_state, INPD, pe_w, 128, (long)INPD * UU,
        p_center, 128, INPD,
        p_lists, p_cnt, p_ch, p_cl);

    // 4. qr = center @ Bk2   (N x 1024, K=128) — fp16 2-pass
    mma_pre<128><<<dim3(128, 8), 256, SMEM_PRE(128)>>>(
        p_ch, p_cl, p_bk, 128,
        p_qr, 1024, nullptr, nullptr, 0);

    // 5. fused gather / scores / softmax / per-relation weighted sums -> s fp16 planes
    edge_kernel<<<NN, 128>>>(adjacency, relation);

    // 6. out = center + relu(s @ Bv2 + fc_b)   (N x 128, K=1024) — fp16 2-pass
    mma_pre<64><<<dim3(256, 1), 256, SMEM_PRE(64)>>>(
        p_sh, p_sl, p_bv, 1024,
        out, 128, fc_b, p_center, 1);
}

// round 15
// speedup vs baseline: 1.3726x; 1.0791x over previous
#include <cuda_runtime.h>
#include <cuda_bf16.h>
#include <cuda_fp16.h>
#include <cstdint>

#define NN  16384
#define DD  32
#define INPD 256
#define UU  128
#define RR  8
#define ENTT 8

// ---------------- scratch (device globals: no allocation allowed) ----------------
__device__ float g_center[NN * UU];            // (N, U) fp32
__device__ __half g_center_h[NN * UU];         // center hi plane (fp16)
__device__ __half g_center_l[NN * UU];         // center lo plane (fp16)
__device__ float g_qr[NN * RR * UU];           // (N, R*U) fp32
__device__ __half g_sh[NN * RR * UU];          // s plane (fp16, single)
__device__ float g_T[RR * UU * UU];            // T[r] = rel[r] @ k_w
__device__ float g_S[RR * UU * UU];            // S[r] = rel[r] @ v_w
__device__ __half g_BkT[RR * UU * UU];         // Bk2^T fp16: [1024][128]
__device__ __half g_BvT[RR * UU * UU];         // Bv2^T fp16: [128][1024]
__device__ int   g_cnt[ENTT];
__device__ int   g_lists[ENTT * NN];
__device__ int   g_bar;                         // monotone barrier ticket

// ======================= warp-level MMA (HMMA path, plain sm_103) =======================
__device__ __forceinline__ void mma_bf16(float* d,
                                         uint32_t a0, uint32_t a1, uint32_t a2, uint32_t a3,
                                         uint32_t b0, uint32_t b1)
{
    asm volatile(
        "mma.sync.aligned.m16n8k16.row.col.f32.bf16.bf16.f32 "
        "{%0,%1,%2,%3}, {%4,%5,%6,%7}, {%8,%9}, {%0,%1,%2,%3};"
        : "+f"(d[0]), "+f"(d[1]), "+f"(d[2]), "+f"(d[3])
        : "r"(a0), "r"(a1), "r"(a2), "r"(a3), "r"(b0), "r"(b1));
}
__device__ __forceinline__ void mma_f16(float* d,
                                        uint32_t a0, uint32_t a1, uint32_t a2, uint32_t a3,
                                        uint32_t b0, uint32_t b1)
{
    asm volatile(
        "mma.sync.aligned.m16n8k16.row.col.f32.f16.f16.f32 "
        "{%0,%1,%2,%3}, {%4,%5,%6,%7}, {%8,%9}, {%0,%1,%2,%3};"
        : "+f"(d[0]), "+f"(d[1]), "+f"(d[2]), "+f"(d[3])
        : "r"(a0), "r"(a1), "r"(a2), "r"(a3), "r"(b0), "r"(b1));
}

__device__ __forceinline__ void ldm_x4(uint32_t& r0, uint32_t& r1, uint32_t& r2, uint32_t& r3,
                                       uint32_t addr)
{
    asm volatile("ldmatrix.sync.aligned.m8n8.x4.shared.b16 {%0,%1,%2,%3}, [%4];"
                 : "=r"(r0), "=r"(r1), "=r"(r2), "=r"(r3) : "r"(addr));
}

__device__ __forceinline__ void cp16(uint32_t dst, const void* src, int sz) {
    asm volatile("cp.async.ca.shared.global [%0], [%1], 16, %2;"
                 :: "r"(dst), "l"(src), "r"(sz) : "memory");
}
#define CP_COMMIT() asm volatile("cp.async.commit_group;" ::: "memory")
#define CP_WAIT1()  asm volatile("cp.async.wait_group 1;" ::: "memory")
#define CP_WAIT0()  asm volatile("cp.async.wait_group 0;" ::: "memory")

// XOR swizzle at 16B-chunk granularity (rows are 16 words of packed 16-bit pairs).
__device__ __forceinline__ int swz(int row, int c) {
    return row * 16 + ((c ^ (row & 3) ^ ((row >> 2) & 1)) << 2);
}

__device__ __forceinline__ uint32_t pack_split_bf(float x, float y, uint32_t& lo) {
    __nv_bfloat16 hx = __float2bfloat16(x), hy = __float2bfloat16(y);
    __nv_bfloat16 lx = __float2bfloat16(x - __bfloat162float(hx));
    __nv_bfloat16 ly = __float2bfloat16(y - __bfloat162float(hy));
    lo = ((uint32_t)__bfloat16_as_ushort(ly) << 16) | __bfloat16_as_ushort(lx);
    return ((uint32_t)__bfloat16_as_ushort(hy) << 16) | __bfloat16_as_ushort(hx);
}
__device__ __forceinline__ uint32_t pack_split_h(float x, float y, uint32_t& lo) {
    __half hx = __float2half_rn(x), hy = __float2half_rn(y);
    __half lx = __float2half_rn(x - __half2float(hx));
    __half ly = __float2half_rn(y - __half2float(hy));
    lo = ((uint32_t)__half_as_ushort(ly) << 16) | __half_as_ushort(lx);
    return ((uint32_t)__half_as_ushort(hy) << 16) | __half_as_ushort(hx);
}

// ======================= fp16 NP-pass GEMM (3-stage cp.async + ldmatrix) ====================
// C[MT x 128] = (Ah [+ Al]) @ B^T ; NP fp16 A planes [M][K], single BT plane [N][K].
#define STGW(MT, NP) ((NP)*(MT)*16 + 128*16)
#define SMEM_PRE(MT, NP) (3 * STGW(MT, NP) * 4)

template<int MT, int NP>
__device__ __forceinline__ void issue_chunk(
    uint32_t stg_base, int kc,
    const __half* Ah, const __half* Al, const __half* B,
    int K, int m0, int n0, int tid)
{
#pragma unroll
    for (int it = 0; it < MT / 64; it++) {
        int lin = tid + it * 256;
        int row = lin >> 2, c = lin & 3;
        int wd = swz(row, c);
        long off = (long)(m0 + row) * K + kc * 32 + c * 8;
        cp16(stg_base + wd * 4, Ah + off, 16);
        if (NP == 2) cp16(stg_base + (MT * 16 + wd) * 4, Al + off, 16);
    }
#pragma unroll
    for (int it = 0; it < 2; it++) {
        int lin = tid + it * 256;
        int row = lin >> 2, c = lin & 3;
        int wd = swz(row, c);
        long off = (long)(n0 + row) * K + kc * 32 + c * 8;
        cp16(stg_base + (NP * MT * 16 + wd) * 4, B + off, 16);
    }
}

template<int MT, int NP>
__global__ __launch_bounds__(256, 2) void mma_pre(
    const __half* __restrict__ Ah, const __half* __restrict__ Al,
    const __half* __restrict__ B,
    int K,
    float* __restrict__ C, int ldc,
    const float* __restrict__ bias, const float* __restrict__ addsrc, int do_relu)
{
    constexpr int NI = MT / 32;
    extern __shared__ char smem[];
    uint32_t sb0 = (uint32_t)__cvta_generic_to_shared(smem);

    const int tid  = threadIdx.x;
    const int lane = tid & 31;
    const int w    = tid >> 5;
    const int wm   = w >> 2;
    const int wn   = w & 3;
    const int q    = lane >> 2;
    const int s4   = lane & 3;
    const int lrow = lane & 7;
    const int seg  = lane >> 3;
    const int m0   = blockIdx.x * MT;
    const int n0   = blockIdx.y * 128;

    float acc[NI][4][4];
#pragma unroll
    for (int i = 0; i < NI; i++)
#pragma unroll
        for (int j = 0; j < 4; j++)
#pragma unroll
            for (int r = 0; r < 4; r++) acc[i][j][r] = 0.f;

    const int nk = K / 32;
    issue_chunk<MT, NP>(sb0, 0, Ah, Al, B, K, m0, n0, tid);
    CP_COMMIT();
    issue_chunk<MT, NP>(sb0 + STGW(MT, NP) * 4, 1, Ah, Al, B, K, m0, n0, tid);
    CP_COMMIT();

    for (int kt = 0; kt < nk; kt++) {
        CP_WAIT1();
        __syncthreads();

        const uint32_t stg = sb0 + (kt % 3) * STGW(MT, NP) * 4;
        const uint32_t oB  = stg + NP * MT * 16 * 4;

#pragma unroll
        for (int st = 0; st < 2; st++) {
            const int c0 = st * 2;
            const int achk = c0 + (seg >> 1);
            const int aoff = lrow + (seg & 1) * 8;
            const int bchk = c0 + (seg & 1);
            const int bsel = (seg >> 1);

            uint32_t aR[NI][4], bR[4][2];

            // --- load B (single plane) ---
#pragma unroll
            for (int jp = 0; jp < 2; jp++) {
                int bcol = wn * 32 + (jp * 2 + bsel) * 8 + lrow;
                ldm_x4(bR[jp * 2][0], bR[jp * 2][1], bR[jp * 2 + 1][0], bR[jp * 2 + 1][1],
                       oB + swz(bcol, bchk) * 4);
            }
#pragma unroll
            for (int p = 0; p < NP; p++) {
                const uint32_t oA = stg + p * MT * 16 * 4;
#pragma unroll
                for (int i = 0; i < NI; i++) {
                    int arow = wm * (MT / 2) + i * 16 + aoff;
                    ldm_x4(aR[i][0], aR[i][1], aR[i][2], aR[i][3], oA + swz(arow, achk) * 4);
                }
#pragma unroll
                for (int j = 0; j < 4; j++)
#pragma unroll
                    for (int i = 0; i < NI; i++)
                        mma_f16(acc[i][j], aR[i][0], aR[i][1], aR[i][2], aR[i][3],
                                bR[j][0], bR[j][1]);
            }
        }
        if (kt + 2 < nk)
            issue_chunk<MT, NP>(sb0 + ((kt + 2) % 3) * STGW(MT, NP) * 4, kt + 2,
                                Ah, Al, B, K, m0, n0, tid);
        CP_COMMIT();
    }

    // ---- epilogue ----
#pragma unroll
    for (int i = 0; i < NI; i++) {
        int r0 = m0 + wm * (MT / 2) + i * 16 + q;
#pragma unroll
        for (int j = 0; j < 4; j++) {
            int cc = n0 + wn * 32 + j * 8 + s4 * 2;
            float bx = 0.f, by = 0.f;
            if (bias) { bx = bias[cc]; by = bias[cc + 1]; }
#pragma unroll
            for (int hrow = 0; hrow < 2; hrow++) {
                int rr = r0 + hrow * 8;
                float vx = acc[i][j][hrow * 2 + 0] + bx;
                float vy = acc[i][j][hrow * 2 + 1] + by;
                if (do_relu) { vx = fmaxf(vx, 0.f); vy = fmaxf(vy, 0.f); }
                if (addsrc) {
                    const float2 av = *reinterpret_cast<const float2*>(addsrc + (long)rr * ldc + cc);
                    vx += av.x; vy += av.y;
                }
                *reinterpret_cast<float2*>(C + (long)rr * ldc + cc) = make_float2(vx, vy);
            }
        }
    }
}

// ======================= fp32-input pipelined MMA (center: gather + 3-pass bf16) =============
#define SROW 17
#define SMEM_MMA (512 + 128*256 + 32768 + 2*128*SROW*4 + 2*128*SROW*4)

__global__ __launch_bounds__(256) void mma_gemm_f32(
    const float* __restrict__ A, int lda,
    const float* __restrict__ B, int ldb, long sBz,
    float* __restrict__ C, int ldc, int K,
    const int* __restrict__ rowlists, const int* __restrict__ cnts,
    __half* __restrict__ Ch, __half* __restrict__ Cl)
{
    constexpr int MT = 128;
    constexpr int NI = 4;
    extern __shared__ char smem[];
    int*      rowidx = (int*)smem;
    float*    rawA   = (float*)(smem + 512);
    float*    rawB   = (float*)(smem + 512 + MT * 256);
    uint32_t* sAb    = (uint32_t*)(smem + 512 + MT * 256 + 32768);
    uint32_t* sBb    = sAb + 2 * MT * SROW;

    const int tid  = threadIdx.x;
    const int lane = tid & 31;
    const int w    = tid >> 5;
    const int wm   = w >> 2;
    const int wn   = w & 3;
    const int m0   = blockIdx.x * MT;
    const int n0   = blockIdx.y * 128;
    const int z    = blockIdx.z;

    int rows = cnts[z];
    if (m0 >= rows) return;
    const int* rl = rowlists + z * NN;
    B += z * sBz;

    if (tid < MT) {
        int g = m0 + tid;
        rowidx[tid] = (g < rows) ? rl[g] : -1;
    }
    __syncthreads();

    float acc[NI][4][4];
#pragma unroll
    for (int i = 0; i < NI; i++)
#pragma unroll
        for (int j = 0; j < 4; j++)
#pragma unroll
            for (int r = 0; r < 4; r++) acc[i][j][r] = 0.f;

    const int nk = K / 32;
    {
#pragma unroll
        for (int it = 0; it < NI; it++) {
            int lin = tid + it * 256;
            int row = lin >> 3, f4 = lin & 7;
            int ar = rowidx[row];
            const float* src = (ar >= 0) ? (A + (long)ar * lda + f4 * 4) : A;
            cp16((uint32_t)__cvta_generic_to_shared(rawA + row * 32 + f4 * 4), src,
                 (ar >= 0) ? 16 : 0);
        }
#pragma unroll
        for (int it = 0; it < 4; it++) {
            int lin = tid + it * 256;
            int kk = lin >> 5, n4 = (lin & 31) * 4;
            cp16((uint32_t)__cvta_generic_to_shared(rawB + kk * 128 + n4),
                 B + (long)kk * ldb + n0 + n4, 16);
        }
        CP_COMMIT();
    }

    for (int kt = 0; kt < nk; kt++) {
        const int cur = kt & 1;
        if (kt + 1 < nk) {
            const int nxt = cur ^ 1;
            const int k0 = (kt + 1) * 32;
#pragma unroll
            for (int it = 0; it < NI; it++) {
                int lin = tid + it * 256;
                int row = lin >> 3, f4 = lin & 7;
                int ar = rowidx[row];
                const float* src = (ar >= 0) ? (A + (long)ar * lda + k0 + f4 * 4) : A;
                cp16((uint32_t)__cvta_generic_to_shared(rawA + nxt * MT * 32 + row * 32 + f4 * 4),
                     src, (ar >= 0) ? 16 : 0);
            }
#pragma unroll
            for (int it = 0; it < 4; it++) {
                int lin = tid + it * 256;
                int kk = lin >> 5, n4 = (lin & 31) * 4;
                cp16((uint32_t)__cvta_generic_to_shared(rawB + nxt * 4096 + kk * 128 + n4),
                     B + (long)(k0 + kk) * ldb + n0 + n4, 16);
            }
            CP_COMMIT();
            CP_WAIT1();
        } else {
            CP_WAIT0();
        }
        __syncthreads();

        const float* rA = rawA + cur * MT * 32;
#pragma unroll
        for (int it = 0; it < NI; it++) {
            int lin = tid + it * 256;
            int row = lin >> 3, f4 = lin & 7;
            float4 v = *reinterpret_cast<const float4*>(rA + row * 32 + f4 * 4);
            uint32_t l0, l1;
            uint32_t h0 = pack_split_bf(v.x, v.y, l0);
            uint32_t h1 = pack_split_bf(v.z, v.w, l1);
            int idx = row * SROW + f4 * 2;
            sAb[idx]                 = h0;
            sAb[idx + 1]             = h1;
            sAb[MT * SROW + idx]     = l0;
            sAb[MT * SROW + idx + 1] = l1;
        }
        const float* rB = rawB + cur * 4096;
#pragma unroll
        for (int it = 0; it < 4; it++) {
            int lin = tid + it * 256;
            int kk = lin >> 5, n4 = (lin & 31) * 4;
            float4 v = *reinterpret_cast<const float4*>(rB + kk * 128 + n4);
            float vv[4] = {v.x, v.y, v.z, v.w};
            __nv_bfloat16* pH = reinterpret_cast<__nv_bfloat16*>(sBb);
            __nv_bfloat16* pL = reinterpret_cast<__nv_bfloat16*>(sBb + 128 * SROW);
#pragma unroll
            for (int j = 0; j < 4; j++) {
                __nv_bfloat16 h = __float2bfloat16(vv[j]);
                __nv_bfloat16 l = __float2bfloat16(vv[j] - __bfloat162float(h));
                int bidx = (n4 + j) * (2 * SROW) + kk;
                pH[bidx] = h;
                pL[bidx] = l;
            }
        }
        __syncthreads();

#pragma unroll
        for (int st = 0; st < 2; st++) {
            int k2 = st * 8 + (lane & 3);
            uint32_t a[NI][4];
#pragma unroll
            for (int p = 0; p < 3; p++) {
                const uint32_t* pA = sAb + ((p == 2) ? MT * SROW : 0);
                const uint32_t* pB = sBb + ((p == 1) ? 128 * SROW : 0);
                if (p != 1) {
#pragma unroll
                    for (int i = 0; i < NI; i++) {
                        int r = wm * (MT / 2) + i * 16 + (lane >> 2);
                        a[i][0] = pA[r * SROW + k2];
                        a[i][1] = pA[(r + 8) * SROW + k2];
                        a[i][2] = pA[r * SROW + k2 + 4];
                        a[i][3] = pA[(r + 8) * SROW + k2 + 4];
                    }
                }
#pragma unroll
                for (int j = 0; j < 4; j++) {
                    int c = wn * 32 + j * 8 + (lane >> 2);
                    uint32_t b0 = pB[c * SROW + k2];
                    uint32_t b1 = pB[c * SROW + k2 + 4];
#pragma unroll
                    for (int i = 0; i < NI; i++)
                        mma_bf16(acc[i][j], a[i][0], a[i][1], a[i][2], a[i][3], b0, b1);
                }
            }
        }
    }

    // epilogue: fp32 C + fp16 hi/lo planes (scatter via rowidx)
#pragma unroll
    for (int i = 0; i < NI; i++) {
        int lr0 = wm * (MT / 2) + i * 16 + (lane >> 2);
#pragma unroll
        for (int j = 0; j < 4; j++) {
            int cc = n0 + wn * 32 + j * 8 + (lane & 3) * 2;
#pragma unroll
            for (int hrow = 0; hrow < 2; hrow++) {
                int rr = rowidx[lr0 + hrow * 8];
                if (rr < 0) continue;
                float vx = acc[i][j][hrow * 2 + 0];
                float vy = acc[i][j][hrow * 2 + 1];
                *reinterpret_cast<float2*>(C + (long)rr * ldc + cc) = make_float2(vx, vy);
                uint32_t pl, ph = pack_split_h(vx, vy, pl);
                reinterpret_cast<uint32_t*>(Ch)[((long)rr * ldc + cc) >> 1] = ph;
                reinterpret_cast<uint32_t*>(Cl)[((long)rr * ldc + cc) >> 1] = pl;
            }
        }
    }
}

// ---------------- 32x128x128 SIMT tile (prep GEMMs) ----------------
__device__ __forceinline__ void gemm32(const float* __restrict__ A,
                                       const float* __restrict__ B,
                                       float* __restrict__ Cf32,
                                       float alpha, int transB,
                                       __half* oh, int o_ld, int rowbase, int colbase)
{
    __shared__ float As[32][33];
    __shared__ float Bs[32][128];
    int tid = threadIdx.x, tx = tid & 15, ty = tid >> 4;
    float acc[2][8];
#pragma unroll
    for (int i = 0; i < 2; i++)
#pragma unroll
        for (int j = 0; j < 8; j++) acc[i][j] = 0.f;

    for (int kt = 0; kt < 128; kt += 32) {
#pragma unroll
        for (int j = 0; j < 4; j++) {
            int lin = tid + j * 256;
            int lr = lin >> 5, lc = lin & 31;
            As[lr][lc] = A[lr * 128 + kt + lc];
        }
#pragma unroll
        for (int j = 0; j < 16; j++) {
            int lin = tid + j * 256;
            int br = lin >> 7, bc = lin & 127;
            Bs[br][bc] = transB ? B[bc * 128 + kt + br] : B[(kt + br) * 128 + bc];
        }
        __syncthreads();
#pragma unroll
        for (int kk = 0; kk < 32; kk++) {
            float bv[8];
#pragma unroll
            for (int j = 0; j < 8; j++) bv[j] = Bs[kk][tx + 16 * j];
#pragma unroll
            for (int i = 0; i < 2; i++) {
                float av = As[ty * 2 + i][kk];
#pragma unroll
                for (int j = 0; j < 8; j++) acc[i][j] += av * bv[j];
            }
        }
        __syncthreads();
    }
    if (Cf32) {
#pragma unroll
        for (int i = 0; i < 2; i++)
#pragma unroll
            for (int j = 0; j < 8; j++)
                Cf32[(ty * 2 + i) * 128 + tx + 16 * j] = acc[i][j] * alpha;
    } else {
#pragma unroll
        for (int i = 0; i < 2; i++) {
            int gr = rowbase + ty * 2 + i;
#pragma unroll
            for (int j = 0; j < 8; j++) {
                int gc = colbase + tx + 16 * j;
                oh[(long)gc * o_ld + gr] = __float2half_rn(acc[i][j] * alpha);
            }
        }
    }
}

// prep_fused (128 blocks):
//   blocks 0-63 : phase1 T/S -> barrier -> phase2 BkT/BvT fp16 planes
//   blocks 64-127: barrier -> entity partition (g_cnt zeroed by block 0 pre-barrier)
__global__ __launch_bounds__(256) void prep_fused(const float* __restrict__ rel_w,
                                                  const float* __restrict__ k_w,
                                                  const float* __restrict__ v_w,
                                                  const float* __restrict__ q_w,
                                                  const float* __restrict__ fc_w,
                                                  const int* __restrict__ point_enc)
{
    int b = blockIdx.x;
    int tid = threadIdx.x;

    if (b == 0 && tid < ENTT) g_cnt[tid] = 0;

    if (b < 64) {   // phase 1
        int j = b >> 2, sub = b & 3;
        int r = j & 7, ph = j >> 3;
        const float* A = rel_w + r * (UU * UU) + sub * 32 * UU;
        const float* B = ph ? v_w : k_w;
        float* C = (ph ? g_S : g_T) + r * (UU * UU) + sub * 32 * UU;
        gemm32(A, B, C, 1.f, 0, nullptr, 0, 0, 0);
    }

    // global barrier (monotone ticket: 128 arrivals per replay, no reset needed)
    __syncthreads();
    if (tid == 0) {
        __threadfence();
        int ticket = atomicAdd(&g_bar, 1);
        int target = ((ticket >> 7) + 1) << 7;
        while (atomicAdd(&g_bar, 0) < target) __nanosleep(64);
        __threadfence();
    }
    __syncthreads();

    if (b < 64) {   // phase 2
        int j = b >> 2, sub = b & 3;
        if (j < 8) {
            int r = j;
            gemm32(q_w + sub * 32 * UU, g_T + r * (UU * UU), nullptr,
                   1.f / 128.f, 1, g_BkT, 128, sub * 32, r * UU);
        } else {
            int r = j - 8;
            gemm32(g_S + r * (UU * UU) + sub * 32 * UU, fc_w, nullptr,
                   1.f, 0, g_BvT, 1024, r * UU + sub * 32, 0);
        }
    } else {        // entity partition (64 blocks x 256 = NN threads)
        int n = (b - 64) * 256 + tid;
        int e = point_enc[n];
        int pos = atomicAdd(&g_cnt[e], 1);
        g_lists[e * NN + pos] = n;
    }
}

// ---------------- fused gather / score / softmax / weighted-scatter ----------------
__global__ __launch_bounds__(128) void edge_kernel(const int* __restrict__ adjacency,
                                                   const int* __restrict__ relation)
{
    __shared__ float xs[DD][UU];
    __shared__ float aw[RR][DD];
    __shared__ float scores[DD];
    __shared__ int adjs[DD];
    __shared__ int rels[DD];

    int n = blockIdx.x;
    int tid = threadIdx.x, lane = tid & 31, w = tid >> 5;

    if (tid < DD) {
        adjs[tid] = adjacency[n * DD + tid];
        rels[tid] = relation[n * DD + tid];
    }
    __syncthreads();

#pragma unroll
    for (int i = 0; i < 8; i++) {
        int d = w * 8 + i;
        int idx = adjs[d];
        float4 v = (idx > 0)
            ? reinterpret_cast<const float4*>(g_center + (idx - 1) * UU)[lane]
            : make_float4(0.f, 0.f, 0.f, 0.f);
        reinterpret_cast<float4*>(&xs[d][0])[lane] = v;
    }
    __syncwarp();

    const float* qbase = g_qr + n * (RR * UU);
#pragma unroll
    for (int i = 0; i < 8; i++) {
        int d = w * 8 + i;
        int r = rels[d];
        const float* q = qbase + r * UU;
        float s = 0.f;
#pragma unroll
        for (int k2 = 0; k2 < 4; k2++) {
            int c = lane + 32 * k2;
            s += q[c] * xs[d][c];
        }
#pragma unroll
        for (int off = 16; off > 0; off >>= 1) s += __shfl_xor_sync(0xffffffffu, s, off);
        if (lane == 0) scores[d] = (r == 0) ? -1e9f : s;
    }
    __syncthreads();

    if (w == 0) {
        float v = scores[lane];
        float m = v;
#pragma unroll
        for (int off = 16; off > 0; off >>= 1) m = fmaxf(m, __shfl_xor_sync(0xffffffffu, m, off));
        float e = __expf(v - m);
        float sum = e;
#pragma unroll
        for (int off = 16; off > 0; off >>= 1) sum += __shfl_xor_sync(0xffffffffu, sum, off);
        float a = e / sum;
        int r = rels[lane];
#pragma unroll
        for (int rr = 0; rr < RR; rr++) aw[rr][lane] = (r == rr) ? a : 0.f;
    }
    __syncthreads();

    float acc[RR];
#pragma unroll
    for (int r = 0; r < RR; r++) acc[r] = 0.f;
#pragma unroll
    for (int d = 0; d < DD; d++) {
        float x = xs[d][tid];
#pragma unroll
        for (int r = 0; r < RR; r++) acc[r] += aw[r][d] * x;
    }
    __half* sph = g_sh + (long)n * (RR * UU) + tid;
#pragma unroll
    for (int r = 0; r < RR; r++)
        sph[r * UU] = __float2half_rn(acc[r]);
}

// ---------------- launch ----------------
extern "C" void kernel_launch(void* const* d_in, const int* in_sizes, int n_in,
                              void* d_out, int out_size)
{
    const float* node_state = (const float*)d_in[0];
    const int*   adjacency  = (const int*)d_in[1];
    const int*   point_enc  = (const int*)d_in[2];
    const int*   relation   = (const int*)d_in[3];
    const float* pe_w       = (const float*)d_in[4];
    const float* rel_w      = (const float*)d_in[5];
    const float* q_w        = (const float*)d_in[6];
    const float* k_w        = (const float*)d_in[7];
    const float* v_w        = (const float*)d_in[8];
    const float* fc_w       = (const float*)d_in[9];
    const float* fc_b       = (const float*)d_in[10];
    float* out = (float*)d_out;

    float *p_center, *p_qr;
    __half *p_ch, *p_cl, *p_sh, *p_bk, *p_bv;
    int *p_cnt, *p_lists;
    cudaGetSymbolAddress((void**)&p_center, g_center);
    cudaGetSymbolAddress((void**)&p_qr,     g_qr);
    cudaGetSymbolAddress((void**)&p_ch,     g_center_h);
    cudaGetSymbolAddress((void**)&p_cl,     g_center_l);
    cudaGetSymbolAddress((void**)&p_sh,     g_sh);
    cudaGetSymbolAddress((void**)&p_bk,     g_BkT);
    cudaGetSymbolAddress((void**)&p_bv,     g_BvT);
    cudaGetSymbolAddress((void**)&p_cnt,    g_cnt);
    cudaGetSymbolAddress((void**)&p_lists,  g_lists);

    cudaFuncSetAttribute(mma_gemm_f32, cudaFuncAttributeMaxDynamicSharedMemorySize, SMEM_MMA);
    cudaFuncSetAttribute((const void*)mma_pre<128, 2>, cudaFuncAttributeMaxDynamicSharedMemorySize, SMEM_PRE(128, 2));
    cudaFuncSetAttribute((const void*)mma_pre<64, 1>,  cudaFuncAttributeMaxDynamicSharedMemorySize, SMEM_PRE(64, 1));

    // 1. prep + partition (one fused launch): T/S -> barrier -> BkT/BvT | partition
    prep_fused<<<128, 256>>>(rel_w, k_w, v_w, q_w, fc_w, point_enc);

    // 2. center = gathered GEMM (fp32 in, 3-pass bf16); emits fp32 + fp16 hi/lo planes
    mma_gemm_f32<<<dim3(32, 1, 8), 256, SMEM_MMA>>>(
        node_state, INPD, pe_w, 128, (long)INPD * UU,
        p_center, 128, INPD,
        p_lists, p_cnt, p_ch, p_cl);

    // 3. qr = center @ Bk2   (N x 1024, K=128) — fp16 2-pass
    mma_pre<128, 2><<<dim3(128, 8), 256, SMEM_PRE(128, 2)>>>(
        p_ch, p_cl, p_bk, 128,
        p_qr, 1024, nullptr, nullptr, 0);

    // 4. fused gather / scores / softmax / per-relation weighted sums -> s fp16 plane
    edge_kernel<<<NN, 128>>>(adjacency, relation);

    // 5. out = center + relu(s @ Bv2 + fc_b)   (N x 128, K=1024) — fp16 1-pass
    mma_pre<64, 1><<<dim3(256, 1), 256, SMEM_PRE(64, 1)>>>(
        p_sh, nullptr, p_bv, 1024,
        out, 128, fc_b, p_center, 1);
}

// round 16
// speedup vs baseline: 1.5632x; 1.1389x over previous
#include <cuda_runtime.h>
#include <cuda_bf16.h>
#include <cuda_fp16.h>
#include <cstdint>

#define NN  16384
#define DD  32
#define INPD 256
#define UU  128
#define RR  8
#define ENTT 8

// ---------------- scratch (device globals: no allocation allowed) ----------------
__device__ float g_center[NN * UU];            // (N, U) fp32
__device__ __half g_center_h[NN * UU];         // center hi plane (fp16)
__device__ __half g_center_l[NN * UU];         // center lo plane (fp16)
__device__ __half g_qr_h[NN * RR * UU];        // qr fp16 plane (N, 1024)
__device__ __half g_sh[NN * RR * UU];          // s plane (fp16, single)
__device__ float g_T[RR * UU * UU];            // T[r] = rel[r] @ k_w
__device__ float g_S[RR * UU * UU];            // S[r] = rel[r] @ v_w
__device__ __half g_BkT[RR * UU * UU];         // Bk2^T fp16: [1024][128]
__device__ __half g_BvT[RR * UU * UU];         // Bv2^T fp16: [128][1024]
__device__ int   g_cnt[ENTT];
__device__ int   g_lists[ENTT * NN];
__device__ int   g_bar;                         // monotone barrier ticket

// ======================= warp-level MMA (HMMA path, plain sm_103) =======================
__device__ __forceinline__ void mma_bf16(float* d,
                                         uint32_t a0, uint32_t a1, uint32_t a2, uint32_t a3,
                                         uint32_t b0, uint32_t b1)
{
    asm volatile(
        "mma.sync.aligned.m16n8k16.row.col.f32.bf16.bf16.f32 "
        "{%0,%1,%2,%3}, {%4,%5,%6,%7}, {%8,%9}, {%0,%1,%2,%3};"
        : "+f"(d[0]), "+f"(d[1]), "+f"(d[2]), "+f"(d[3])
        : "r"(a0), "r"(a1), "r"(a2), "r"(a3), "r"(b0), "r"(b1));
}
__device__ __forceinline__ void mma_f16(float* d,
                                        uint32_t a0, uint32_t a1, uint32_t a2, uint32_t a3,
                                        uint32_t b0, uint32_t b1)
{
    asm volatile(
        "mma.sync.aligned.m16n8k16.row.col.f32.f16.f16.f32 "
        "{%0,%1,%2,%3}, {%4,%5,%6,%7}, {%8,%9}, {%0,%1,%2,%3};"
        : "+f"(d[0]), "+f"(d[1]), "+f"(d[2]), "+f"(d[3])
        : "r"(a0), "r"(a1), "r"(a2), "r"(a3), "r"(b0), "r"(b1));
}

__device__ __forceinline__ void ldm_x4(uint32_t& r0, uint32_t& r1, uint32_t& r2, uint32_t& r3,
                                       uint32_t addr)
{
    asm volatile("ldmatrix.sync.aligned.m8n8.x4.shared.b16 {%0,%1,%2,%3}, [%4];"
                 : "=r"(r0), "=r"(r1), "=r"(r2), "=r"(r3) : "r"(addr));
}

__device__ __forceinline__ void cp16(uint32_t dst, const void* src, int sz) {
    asm volatile("cp.async.ca.shared.global [%0], [%1], 16, %2;"
                 :: "r"(dst), "l"(src), "r"(sz) : "memory");
}
#define CP_COMMIT() asm volatile("cp.async.commit_group;" ::: "memory")
#define CP_WAIT1()  asm volatile("cp.async.wait_group 1;" ::: "memory")
#define CP_WAIT0()  asm volatile("cp.async.wait_group 0;" ::: "memory")

// XOR swizzle at 16B-chunk granularity (rows are 16 words of packed 16-bit pairs).
__device__ __forceinline__ int swz(int row, int c) {
    return row * 16 + ((c ^ (row & 3) ^ ((row >> 2) & 1)) << 2);
}

__device__ __forceinline__ uint32_t pack_split_bf(float x, float y, uint32_t& lo) {
    __nv_bfloat16 hx = __float2bfloat16(x), hy = __float2bfloat16(y);
    __nv_bfloat16 lx = __float2bfloat16(x - __bfloat162float(hx));
    __nv_bfloat16 ly = __float2bfloat16(y - __bfloat162float(hy));
    lo = ((uint32_t)__bfloat16_as_ushort(ly) << 16) | __bfloat16_as_ushort(lx);
    return ((uint32_t)__bfloat16_as_ushort(hy) << 16) | __bfloat16_as_ushort(hx);
}
__device__ __forceinline__ uint32_t pack_split_h(float x, float y, uint32_t& lo) {
    __half hx = __float2half_rn(x), hy = __float2half_rn(y);
    __half lx = __float2half_rn(x - __half2float(hx));
    __half ly = __float2half_rn(y - __half2float(hy));
    lo = ((uint32_t)__half_as_ushort(ly) << 16) | __half_as_ushort(lx);
    return ((uint32_t)__half_as_ushort(hy) << 16) | __half_as_ushort(hx);
}

// ======================= fp16 NP-pass GEMM (3-stage cp.async + ldmatrix) ====================
// C[MT x 128] = (Ah [+ Al]) @ B^T ; NP fp16 A planes [M][K], single BT plane [N][K].
// Output: fp16 plane Ch if non-null, else fp32 C.
#define STGW(MT, NP) ((NP)*(MT)*16 + 128*16)
#define SMEM_PRE(MT, NP) (3 * STGW(MT, NP) * 4)

template<int MT, int NP>
__device__ __forceinline__ void issue_chunk(
    uint32_t stg_base, int kc,
    const __half* Ah, const __half* Al, const __half* B,
    int K, int m0, int n0, int tid)
{
#pragma unroll
    for (int it = 0; it < MT / 64; it++) {
        int lin = tid + it * 256;
        int row = lin >> 2, c = lin & 3;
        int wd = swz(row, c);
        long off = (long)(m0 + row) * K + kc * 32 + c * 8;
        cp16(stg_base + wd * 4, Ah + off, 16);
        if (NP == 2) cp16(stg_base + (MT * 16 + wd) * 4, Al + off, 16);
    }
#pragma unroll
    for (int it = 0; it < 2; it++) {
        int lin = tid + it * 256;
        int row = lin >> 2, c = lin & 3;
        int wd = swz(row, c);
        long off = (long)(n0 + row) * K + kc * 32 + c * 8;
        cp16(stg_base + (NP * MT * 16 + wd) * 4, B + off, 16);
    }
}

template<int MT, int NP>
__global__ __launch_bounds__(256, 2) void mma_pre(
    const __half* __restrict__ Ah, const __half* __restrict__ Al,
    const __half* __restrict__ B,
    int K,
    float* __restrict__ C, __half* __restrict__ Ch, int ldc,
    const float* __restrict__ bias, const float* __restrict__ addsrc, int do_relu)
{
    constexpr int NI = MT / 32;
    extern __shared__ char smem[];
    uint32_t sb0 = (uint32_t)__cvta_generic_to_shared(smem);

    const int tid  = threadIdx.x;
    const int lane = tid & 31;
    const int w    = tid >> 5;
    const int wm   = w >> 2;
    const int wn   = w & 3;
    const int q    = lane >> 2;
    const int s4   = lane & 3;
    const int lrow = lane & 7;
    const int seg  = lane >> 3;
    const int m0   = blockIdx.x * MT;
    const int n0   = blockIdx.y * 128;

    float acc[NI][4][4];
#pragma unroll
    for (int i = 0; i < NI; i++)
#pragma unroll
        for (int j = 0; j < 4; j++)
#pragma unroll
            for (int r = 0; r < 4; r++) acc[i][j][r] = 0.f;

    const int nk = K / 32;
    issue_chunk<MT, NP>(sb0, 0, Ah, Al, B, K, m0, n0, tid);
    CP_COMMIT();
    issue_chunk<MT, NP>(sb0 + STGW(MT, NP) * 4, 1, Ah, Al, B, K, m0, n0, tid);
    CP_COMMIT();

    for (int kt = 0; kt < nk; kt++) {
        CP_WAIT1();
        __syncthreads();

        const uint32_t stg = sb0 + (kt % 3) * STGW(MT, NP) * 4;
        const uint32_t oB  = stg + NP * MT * 16 * 4;

#pragma unroll
        for (int st = 0; st < 2; st++) {
            const int c0 = st * 2;
            const int achk = c0 + (seg >> 1);
            const int aoff = lrow + (seg & 1) * 8;
            const int bchk = c0 + (seg & 1);
            const int bsel = (seg >> 1);

            uint32_t aR[NI][4], bR[4][2];

            // --- load B (single plane) ---
#pragma unroll
            for (int jp = 0; jp < 2; jp++) {
                int bcol = wn * 32 + (jp * 2 + bsel) * 8 + lrow;
                ldm_x4(bR[jp * 2][0], bR[jp * 2][1], bR[jp * 2 + 1][0], bR[jp * 2 + 1][1],
                       oB + swz(bcol, bchk) * 4);
            }
#pragma unroll
            for (int p = 0; p < NP; p++) {
                const uint32_t oA = stg + p * MT * 16 * 4;
#pragma unroll
                for (int i = 0; i < NI; i++) {
                    int arow = wm * (MT / 2) + i * 16 + aoff;
                    ldm_x4(aR[i][0], aR[i][1], aR[i][2], aR[i][3], oA + swz(arow, achk) * 4);
                }
#pragma unroll
                for (int j = 0; j < 4; j++)
#pragma unroll
                    for (int i = 0; i < NI; i++)
                        mma_f16(acc[i][j], aR[i][0], aR[i][1], aR[i][2], aR[i][3],
                                bR[j][0], bR[j][1]);
            }
        }
        if (kt + 2 < nk)
            issue_chunk<MT, NP>(sb0 + ((kt + 2) % 3) * STGW(MT, NP) * 4, kt + 2,
                                Ah, Al, B, K, m0, n0, tid);
        CP_COMMIT();
    }

    // ---- epilogue ----
#pragma unroll
    for (int i = 0; i < NI; i++) {
        int r0 = m0 + wm * (MT / 2) + i * 16 + q;
#pragma unroll
        for (int j = 0; j < 4; j++) {
            int cc = n0 + wn * 32 + j * 8 + s4 * 2;
            float bx = 0.f, by = 0.f;
            if (bias) { bx = bias[cc]; by = bias[cc + 1]; }
#pragma unroll
            for (int hrow = 0; hrow < 2; hrow++) {
                int rr = r0 + hrow * 8;
                float vx = acc[i][j][hrow * 2 + 0] + bx;
                float vy = acc[i][j][hrow * 2 + 1] + by;
                if (do_relu) { vx = fmaxf(vx, 0.f); vy = fmaxf(vy, 0.f); }
                if (addsrc) {
                    const float2 av = *reinterpret_cast<const float2*>(addsrc + (long)rr * ldc + cc);
                    vx += av.x; vy += av.y;
                }
                if (Ch) {
                    __half2 hv = __floats2half2_rn(vx, vy);
                    *reinterpret_cast<__half2*>(Ch + (long)rr * ldc + cc) = hv;
                } else {
                    *reinterpret_cast<float2*>(C + (long)rr * ldc + cc) = make_float2(vx, vy);
                }
            }
        }
    }
}

// ======================= fp32-input pipelined MMA (center: gather + 3-pass bf16) =============
#define SROW 17
#define SMEM_MMA (512 + 128*256 + 32768 + 2*128*SROW*4 + 2*128*SROW*4)

__global__ __launch_bounds__(256) void mma_gemm_f32(
    const float* __restrict__ A, int lda,
    const float* __restrict__ B, int ldb, long sBz,
    float* __restrict__ C, int ldc, int K,
    const int* __restrict__ rowlists, const int* __restrict__ cnts,
    __half* __restrict__ Ch, __half* __restrict__ Cl)
{
    constexpr int MT = 128;
    constexpr int NI = 4;
    extern __shared__ char smem[];
    int*      rowidx = (int*)smem;
    float*    rawA   = (float*)(smem + 512);
    float*    rawB   = (float*)(smem + 512 + MT * 256);
    uint32_t* sAb    = (uint32_t*)(smem + 512 + MT * 256 + 32768);
    uint32_t* sBb    = sAb + 2 * MT * SROW;

    const int tid  = threadIdx.x;
    const int lane = tid & 31;
    const int w    = tid >> 5;
    const int wm   = w >> 2;
    const int wn   = w & 3;
    const int m0   = blockIdx.x * MT;
    const int n0   = blockIdx.y * 128;
    const int z    = blockIdx.z;

    int rows = cnts[z];
    if (m0 >= rows) return;
    const int* rl = rowlists + z * NN;
    B += z * sBz;

    if (tid < MT) {
        int g = m0 + tid;
        rowidx[tid] = (g < rows) ? rl[g] : -1;
    }
    __syncthreads();

    float acc[NI][4][4];
#pragma unroll
    for (int i = 0; i < NI; i++)
#pragma unroll
        for (int j = 0; j < 4; j++)
#pragma unroll
            for (int r = 0; r < 4; r++) acc[i][j][r] = 0.f;

    const int nk = K / 32;
    {
#pragma unroll
        for (int it = 0; it < NI; it++) {
            int lin = tid + it * 256;
            int row = lin >> 3, f4 = lin & 7;
            int ar = rowidx[row];
            const float* src = (ar >= 0) ? (A + (long)ar * lda + f4 * 4) : A;
            cp16((uint32_t)__cvta_generic_to_shared(rawA + row * 32 + f4 * 4), src,
                 (ar >= 0) ? 16 : 0);
        }
#pragma unroll
        for (int it = 0; it < 4; it++) {
            int lin = tid + it * 256;
            int kk = lin >> 5, n4 = (lin & 31) * 4;
            cp16((uint32_t)__cvta_generic_to_shared(rawB + kk * 128 + n4),
                 B + (long)kk * ldb + n0 + n4, 16);
        }
        CP_COMMIT();
    }

    for (int kt = 0; kt < nk; kt++) {
        const int cur = kt & 1;
        if (kt + 1 < nk) {
            const int nxt = cur ^ 1;
            const int k0 = (kt + 1) * 32;
#pragma unroll
            for (int it = 0; it < NI; it++) {
                int lin = tid + it * 256;
                int row = lin >> 3, f4 = lin & 7;
                int ar = rowidx[row];
                const float* src = (ar >= 0) ? (A + (long)ar * lda + k0 + f4 * 4) : A;
                cp16((uint32_t)__cvta_generic_to_shared(rawA + nxt * MT * 32 + row * 32 + f4 * 4),
                     src, (ar >= 0) ? 16 : 0);
            }
#pragma unroll
            for (int it = 0; it < 4; it++) {
                int lin = tid + it * 256;
                int kk = lin >> 5, n4 = (lin & 31) * 4;
                cp16((uint32_t)__cvta_generic_to_shared(rawB + nxt * 4096 + kk * 128 + n4),
                     B + (long)(k0 + kk) * ldb + n0 + n4, 16);
            }
            CP_COMMIT();
            CP_WAIT1();
        } else {
            CP_WAIT0();
        }
        __syncthreads();

        const float* rA = rawA + cur * MT * 32;
#pragma unroll
        for (int it = 0; it < NI; it++) {
            int lin = tid + it * 256;
            int row = lin >> 3, f4 = lin & 7;
            float4 v = *reinterpret_cast<const float4*>(rA + row * 32 + f4 * 4);
            uint32_t l0, l1;
            uint32_t h0 = pack_split_bf(v.x, v.y, l0);
            uint32_t h1 = pack_split_bf(v.z, v.w, l1);
            int idx = row * SROW + f4 * 2;
            sAb[idx]                 = h0;
            sAb[idx + 1]             = h1;
            sAb[MT * SROW + idx]     = l0;
            sAb[MT * SROW + idx + 1] = l1;
        }
        const float* rB = rawB + cur * 4096;
#pragma unroll
        for (int it = 0; it < 4; it++) {
            int lin = tid + it * 256;
            int kk = lin >> 5, n4 = (lin & 31) * 4;
            float4 v = *reinterpret_cast<const float4*>(rB + kk * 128 + n4);
            float vv[4] = {v.x, v.y, v.z, v.w};
            __nv_bfloat16* pH = reinterpret_cast<__nv_bfloat16*>(sBb);
            __nv_bfloat16* pL = reinterpret_cast<__nv_bfloat16*>(sBb + 128 * SROW);
#pragma unroll
            for (int j = 0; j < 4; j++) {
                __nv_bfloat16 h = __float2bfloat16(vv[j]);
                __nv_bfloat16 l = __float2bfloat16(vv[j] - __bfloat162float(h));
                int bidx = (n4 + j) * (2 * SROW) + kk;
                pH[bidx] = h;
                pL[bidx] = l;
            }
        }
        __syncthreads();

#pragma unroll
        for (int st = 0; st < 2; st++) {
            int k2 = st * 8 + (lane & 3);
            uint32_t a[NI][4];
#pragma unroll
            for (int p = 0; p < 3; p++) {
                const uint32_t* pA = sAb + ((p == 2) ? MT * SROW : 0);
                const uint32_t* pB = sBb + ((p == 1) ? 128 * SROW : 0);
                if (p != 1) {
#pragma unroll
                    for (int i = 0; i < NI; i++) {
                        int r = wm * (MT / 2) + i * 16 + (lane >> 2);
                        a[i][0] = pA[r * SROW + k2];
                        a[i][1] = pA[(r + 8) * SROW + k2];
                        a[i][2] = pA[r * SROW + k2 + 4];
                        a[i][3] = pA[(r + 8) * SROW + k2 + 4];
                    }
                }
#pragma unroll
                for (int j = 0; j < 4; j++) {
                    int c = wn * 32 + j * 8 + (lane >> 2);
                    uint32_t b0 = pB[c * SROW + k2];
                    uint32_t b1 = pB[c * SROW + k2 + 4];
#pragma unroll
                    for (int i = 0; i < NI; i++)
                        mma_bf16(acc[i][j], a[i][0], a[i][1], a[i][2], a[i][3], b0, b1);
                }
            }
        }
    }

    // epilogue: fp32 C + fp16 hi/lo planes (scatter via rowidx)
#pragma unroll
    for (int i = 0; i < NI; i++) {
        int lr0 = wm * (MT / 2) + i * 16 + (lane >> 2);
#pragma unroll
        for (int j = 0; j < 4; j++) {
            int cc = n0 + wn * 32 + j * 8 + (lane & 3) * 2;
#pragma unroll
            for (int hrow = 0; hrow < 2; hrow++) {
                int rr = rowidx[lr0 + hrow * 8];
                if (rr < 0) continue;
                float vx = acc[i][j][hrow * 2 + 0];
                float vy = acc[i][j][hrow * 2 + 1];
                *reinterpret_cast<float2*>(C + (long)rr * ldc + cc) = make_float2(vx, vy);
                uint32_t pl, ph = pack_split_h(vx, vy, pl);
                reinterpret_cast<uint32_t*>(Ch)[((long)rr * ldc + cc) >> 1] = ph;
                reinterpret_cast<uint32_t*>(Cl)[((long)rr * ldc + cc) >> 1] = pl;
            }
        }
    }
}

// ---------------- 32x128x128 SIMT tile (prep GEMMs) ----------------
__device__ __forceinline__ void gemm32(const float* __restrict__ A,
                                       const float* __restrict__ B,
                                       float* __restrict__ Cf32,
                                       float alpha, int transB,
                                       __half* oh, int o_ld, int rowbase, int colbase)
{
    __shared__ float As[32][33];
    __shared__ float Bs[32][128];
    int tid = threadIdx.x, tx = tid & 15, ty = tid >> 4;
    float acc[2][8];
#pragma unroll
    for (int i = 0; i < 2; i++)
#pragma unroll
        for (int j = 0; j < 8; j++) acc[i][j] = 0.f;

    for (int kt = 0; kt < 128; kt += 32) {
#pragma unroll
        for (int j = 0; j < 4; j++) {
            int lin = tid + j * 256;
            int lr = lin >> 5, lc = lin & 31;
            As[lr][lc] = A[lr * 128 + kt + lc];
        }
#pragma unroll
        for (int j = 0; j < 16; j++) {
            int lin = tid + j * 256;
            int br = lin >> 7, bc = lin & 127;
            Bs[br][bc] = transB ? B[bc * 128 + kt + br] : B[(kt + br) * 128 + bc];
        }
        __syncthreads();
#pragma unroll
        for (int kk = 0; kk < 32; kk++) {
            float bv[8];
#pragma unroll
            for (int j = 0; j < 8; j++) bv[j] = Bs[kk][tx + 16 * j];
#pragma unroll
            for (int i = 0; i < 2; i++) {
                float av = As[ty * 2 + i][kk];
#pragma unroll
                for (int j = 0; j < 8; j++) acc[i][j] += av * bv[j];
            }
        }
        __syncthreads();
    }
    if (Cf32) {
#pragma unroll
        for (int i = 0; i < 2; i++)
#pragma unroll
            for (int j = 0; j < 8; j++)
                Cf32[(ty * 2 + i) * 128 + tx + 16 * j] = acc[i][j] * alpha;
    } else {
#pragma unroll
        for (int i = 0; i < 2; i++) {
            int gr = rowbase + ty * 2 + i;
#pragma unroll
            for (int j = 0; j < 8; j++) {
                int gc = colbase + tx + 16 * j;
                oh[(long)gc * o_ld + gr] = __float2half_rn(acc[i][j] * alpha);
            }
        }
    }
}

// prep_fused (128 blocks):
//   blocks 0-63 : phase1 T/S -> barrier -> phase2 BkT/BvT fp16 planes
//   blocks 64-127: barrier -> entity partition (g_cnt zeroed by block 0 pre-barrier)
__global__ __launch_bounds__(256) void prep_fused(const float* __restrict__ rel_w,
                                                  const float* __restrict__ k_w,
                                                  const float* __restrict__ v_w,
                                                  const float* __restrict__ q_w,
                                                  const float* __restrict__ fc_w,
                                                  const int* __restrict__ point_enc)
{
    int b = blockIdx.x;
    int tid = threadIdx.x;

    if (b == 0 && tid < ENTT) g_cnt[tid] = 0;

    if (b < 64) {   // phase 1
        int j = b >> 2, sub = b & 3;
        int r = j & 7, ph = j >> 3;
        const float* A = rel_w + r * (UU * UU) + sub * 32 * UU;
        const float* B = ph ? v_w : k_w;
        float* C = (ph ? g_S : g_T) + r * (UU * UU) + sub * 32 * UU;
        gemm32(A, B, C, 1.f, 0, nullptr, 0, 0, 0);
    }

    // global barrier (monotone ticket: 128 arrivals per replay, no reset needed)
    __syncthreads();
    if (tid == 0) {
        __threadfence();
        int ticket = atomicAdd(&g_bar, 1);
        int target = ((ticket >> 7) + 1) << 7;
        while (atomicAdd(&g_bar, 0) < target) __nanosleep(64);
        __threadfence();
    }
    __syncthreads();

    if (b < 64) {   // phase 2
        int j = b >> 2, sub = b & 3;
        if (j < 8) {
            int r = j;
            gemm32(q_w + sub * 32 * UU, g_T + r * (UU * UU), nullptr,
                   1.f / 128.f, 1, g_BkT, 128, sub * 32, r * UU);
        } else {
            int r = j - 8;
            gemm32(g_S + r * (UU * UU) + sub * 32 * UU, fc_w, nullptr,
                   1.f, 0, g_BvT, 1024, r * UU + sub * 32, 0);
        }
    } else {        // entity partition (64 blocks x 256 = NN threads)
        int n = (b - 64) * 256 + tid;
        int e = point_enc[n];
        int pos = atomicAdd(&g_cnt[e], 1);
        g_lists[e * NN + pos] = n;
    }
}

// ---------------- fused gather / score / softmax / weighted-scatter (fp16 path) -------------
__global__ __launch_bounds__(128) void edge_kernel(const int* __restrict__ adjacency,
                                                   const int* __restrict__ relation)
{
    __shared__ uint32_t xs2[DD][UU / 2];   // gathered neighbor embeddings, half2
    __shared__ float aw[RR][DD];           // per-relation masked attention
    __shared__ float scores[DD];
    __shared__ int adjs[DD];
    __shared__ int rels[DD];

    int n = blockIdx.x;
    int tid = threadIdx.x, lane = tid & 31, w = tid >> 5;

    if (tid < DD) {
        adjs[tid] = adjacency[n * DD + tid];
        rels[tid] = relation[n * DD + tid];
    }
    __syncthreads();

    // gather x (fp16 hi plane): warp w rows d = w*8..w*8+7, lane loads uint2 (4 halfs)
#pragma unroll
    for (int i = 0; i < 8; i++) {
        int d = w * 8 + i;
        int idx = adjs[d];
        uint2 v = (idx > 0)
            ? reinterpret_cast<const uint2*>(g_center_h + (long)(idx - 1) * UU)[lane]
            : make_uint2(0u, 0u);
        reinterpret_cast<uint2*>(&xs2[d][0])[lane] = v;
    }
    __syncwarp();

    // scores[d] = qr_h[n, rel[d]] . x[d]   (fp16 x fp16, fp32 accumulate)
    const __half* qbase = g_qr_h + (long)n * (RR * UU);
#pragma unroll
    for (int i = 0; i < 8; i++) {
        int d = w * 8 + i;
        int r = rels[d];
        const uint32_t* q2 = reinterpret_cast<const uint32_t*>(qbase + r * UU);
        float s = 0.f;
#pragma unroll
        for (int k2 = 0; k2 < 2; k2++) {
            int c = lane + 32 * k2;
            float2 qf = __half22float2(*reinterpret_cast<const __half2*>(&q2[c]));
            float2 xf = __half22float2(*reinterpret_cast<const __half2*>(&xs2[d][c]));
            s += qf.x * xf.x + qf.y * xf.y;
        }
#pragma unroll
        for (int off = 16; off > 0; off >>= 1) s += __shfl_xor_sync(0xffffffffu, s, off);
        if (lane == 0) scores[d] = (r == 0) ? -1e9f : s;
    }
    __syncthreads();

    // softmax over D=32 (warp 0), per-relation masked attention
    if (w == 0) {
        float v = scores[lane];
        float m = v;
#pragma unroll
        for (int off = 16; off > 0; off >>= 1) m = fmaxf(m, __shfl_xor_sync(0xffffffffu, m, off));
        float e = __expf(v - m);
        float sum = e;
#pragma unroll
        for (int off = 16; off > 0; off >>= 1) sum += __shfl_xor_sync(0xffffffffu, sum, off);
        float a = e / sum;
        int r = rels[lane];
#pragma unroll
        for (int rr = 0; rr < RR; rr++) aw[rr][lane] = (r == rr) ? a : 0.f;
    }
    __syncthreads();

    // s-phase: thread = (column-pair, relation-half); half2 x, float2 accum
    const int col2 = tid & 63;         // half2 column (covers cols 2*col2, 2*col2+1)
    const int rh   = tid >> 6;         // relations rh*4 .. rh*4+3
    float2 acc[4];
#pragma unroll
    for (int r2 = 0; r2 < 4; r2++) acc[r2] = make_float2(0.f, 0.f);
#pragma unroll
    for (int d = 0; d < DD; d++) {
        float2 xf = __half22float2(*reinterpret_cast<const __half2*>(&xs2[d][col2]));
#pragma unroll
        for (int r2 = 0; r2 < 4; r2++) {
            float a = aw[rh * 4 + r2][d];
            acc[r2].x += a * xf.x;
            acc[r2].y += a * xf.y;
        }
    }
    __half* sp = g_sh + (long)n * (RR * UU);
#pragma unroll
    for (int r2 = 0; r2 < 4; r2++) {
        __half2 hv = __floats2half2_rn(acc[r2].x, acc[r2].y);
        *reinterpret_cast<__half2*>(sp + (rh * 4 + r2) * UU + col2 * 2) = hv;
    }
}

// ---------------- launch ----------------
extern "C" void kernel_launch(void* const* d_in, const int* in_sizes, int n_in,
                              void* d_out, int out_size)
{
    const float* node_state = (const float*)d_in[0];
    const int*   adjacency  = (const int*)d_in[1];
    const int*   point_enc  = (const int*)d_in[2];
    const int*   relation   = (const int*)d_in[3];
    const float* pe_w       = (const float*)d_in[4];
    const float* rel_w      = (const float*)d_in[5];
    const float* q_w        = (const float*)d_in[6];
    const float* k_w        = (const float*)d_in[7];
    const float* v_w        = (const float*)d_in[8];
    const float* fc_w       = (const float*)d_in[9];
    const float* fc_b       = (const float*)d_in[10];
    float* out = (float*)d_out;

    float *p_center;
    __half *p_ch, *p_cl, *p_qrh, *p_sh, *p_bk, *p_bv;
    int *p_cnt, *p_lists;
    cudaGetSymbolAddress((void**)&p_center, g_center);
    cudaGetSymbolAddress((void**)&p_ch,     g_center_h);
    cudaGetSymbolAddress((void**)&p_cl,     g_center_l);
    cudaGetSymbolAddress((void**)&p_qrh,    g_qr_h);
    cudaGetSymbolAddress((void**)&p_sh,     g_sh);
    cudaGetSymbolAddress((void**)&p_bk,     g_BkT);
    cudaGetSymbolAddress((void**)&p_bv,     g_BvT);
    cudaGetSymbolAddress((void**)&p_cnt,    g_cnt);
    cudaGetSymbolAddress((void**)&p_lists,  g_lists);

    cudaFuncSetAttribute(mma_gemm_f32, cudaFuncAttributeMaxDynamicSharedMemorySize, SMEM_MMA);
    cudaFuncSetAttribute((const void*)mma_pre<128, 2>, cudaFuncAttributeMaxDynamicSharedMemorySize, SMEM_PRE(128, 2));
    cudaFuncSetAttribute((const void*)mma_pre<64, 1>,  cudaFuncAttributeMaxDynamicSharedMemorySize, SMEM_PRE(64, 1));

    // 1. prep + partition (one fused launch): T/S -> barrier -> BkT/BvT | partition
    prep_fused<<<128, 256>>>(rel_w, k_w, v_w, q_w, fc_w, point_enc);

    // 2. center = gathered GEMM (fp32 in, 3-pass bf16); emits fp32 + fp16 hi/lo planes
    mma_gemm_f32<<<dim3(32, 1, 8), 256, SMEM_MMA>>>(
        node_state, INPD, pe_w, 128, (long)INPD * UU,
        p_center, 128, INPD,
        p_lists, p_cnt, p_ch, p_cl);

    // 3. qr = center @ Bk2   (N x 1024, K=128) — fp16 2-pass, fp16 output plane
    mma_pre<128, 2><<<dim3(128, 8), 256, SMEM_PRE(128, 2)>>>(
        p_ch, p_cl, p_bk, 128,
        nullptr, p_qrh, 1024, nullptr, nullptr, 0);

    // 4. fused gather / scores / softmax / per-relation weighted sums (fp16 path)
    edge_kernel<<<NN, 128>>>(adjacency, relation);

    // 5. out = center + relu(s @ Bv2 + fc_b)   (N x 128, K=1024) — fp16 1-pass, fp32 out
    mma_pre<64, 1><<<dim3(256, 1), 256, SMEM_PRE(64, 1)>>>(
        p_sh, nullptr, p_bv, 1024,
        out, nullptr, 128, fc_b, p_center, 1);
}

// round 17
// speedup vs baseline: 1.6048x; 1.0266x over previous
#include <cuda_runtime.h>
#include <cuda_bf16.h>
#include <cuda_fp16.h>
#include <cstdint>

#define NN  16384
#define DD  32
#define INPD 256
#define UU  128
#define RR  8
#define ENTT 8

// ---------------- scratch (device globals: no allocation allowed) ----------------
__device__ float g_center[NN * UU];            // (N, U) fp32
__device__ __half g_center_h[NN * UU];         // center hi plane (fp16)
__device__ __half g_center_l[NN * UU];         // center lo plane (fp16)
__device__ __half g_qr_h[NN * RR * UU];        // qr fp16 plane (N, 1024)
__device__ __half g_sh[NN * RR * UU];          // s plane (fp16, single)
__device__ float g_T[RR * UU * UU];            // T[r] = rel[r] @ k_w
__device__ float g_S[RR * UU * UU];            // S[r] = rel[r] @ v_w
__device__ __half g_BkT[RR * UU * UU];         // Bk2^T fp16: [1024][128]
__device__ __half g_BvT[RR * UU * UU];         // Bv2^T fp16: [128][1024]
__device__ int   g_cnt[ENTT];
__device__ int   g_lists[ENTT * NN];
__device__ int   g_bar;                         // monotone barrier ticket

// ======================= warp-level MMA (HMMA path, plain sm_103) =======================
__device__ __forceinline__ void mma_bf16(float* d,
                                         uint32_t a0, uint32_t a1, uint32_t a2, uint32_t a3,
                                         uint32_t b0, uint32_t b1)
{
    asm volatile(
        "mma.sync.aligned.m16n8k16.row.col.f32.bf16.bf16.f32 "
        "{%0,%1,%2,%3}, {%4,%5,%6,%7}, {%8,%9}, {%0,%1,%2,%3};"
        : "+f"(d[0]), "+f"(d[1]), "+f"(d[2]), "+f"(d[3])
        : "r"(a0), "r"(a1), "r"(a2), "r"(a3), "r"(b0), "r"(b1));
}
__device__ __forceinline__ void mma_f16(float* d,
                                        uint32_t a0, uint32_t a1, uint32_t a2, uint32_t a3,
                                        uint32_t b0, uint32_t b1)
{
    asm volatile(
        "mma.sync.aligned.m16n8k16.row.col.f32.f16.f16.f32 "
        "{%0,%1,%2,%3}, {%4,%5,%6,%7}, {%8,%9}, {%0,%1,%2,%3};"
        : "+f"(d[0]), "+f"(d[1]), "+f"(d[2]), "+f"(d[3])
        : "r"(a0), "r"(a1), "r"(a2), "r"(a3), "r"(b0), "r"(b1));
}

__device__ __forceinline__ void ldm_x4(uint32_t& r0, uint32_t& r1, uint32_t& r2, uint32_t& r3,
                                       uint32_t addr)
{
    asm volatile("ldmatrix.sync.aligned.m8n8.x4.shared.b16 {%0,%1,%2,%3}, [%4];"
                 : "=r"(r0), "=r"(r1), "=r"(r2), "=r"(r3) : "r"(addr));
}
__device__ __forceinline__ void ldm_x2_trans(uint32_t& r0, uint32_t& r1, uint32_t addr)
{
    asm volatile("ldmatrix.sync.aligned.m8n8.x2.trans.shared.b16 {%0,%1}, [%2];"
                 : "=r"(r0), "=r"(r1) : "r"(addr));
}

__device__ __forceinline__ void cp16(uint32_t dst, const void* src, int sz) {
    asm volatile("cp.async.ca.shared.global [%0], [%1], 16, %2;"
                 :: "r"(dst), "l"(src), "r"(sz) : "memory");
}
#define CP_COMMIT() asm volatile("cp.async.commit_group;" ::: "memory")
#define CP_WAIT1()  asm volatile("cp.async.wait_group 1;" ::: "memory")
#define CP_WAIT0()  asm volatile("cp.async.wait_group 0;" ::: "memory")

// XOR swizzle at 16B-chunk granularity (rows are 16 words of packed 16-bit pairs).
__device__ __forceinline__ int swz(int row, int c) {
    return row * 16 + ((c ^ (row & 3) ^ ((row >> 2) & 1)) << 2);
}

__device__ __forceinline__ uint32_t pack_split_bf(float x, float y, uint32_t& lo) {
    __nv_bfloat16 hx = __float2bfloat16(x), hy = __float2bfloat16(y);
    __nv_bfloat16 lx = __float2bfloat16(x - __bfloat162float(hx));
    __nv_bfloat16 ly = __float2bfloat16(y - __bfloat162float(hy));
    lo = ((uint32_t)__bfloat16_as_ushort(ly) << 16) | __bfloat16_as_ushort(lx);
    return ((uint32_t)__bfloat16_as_ushort(hy) << 16) | __bfloat16_as_ushort(hx);
}
__device__ __forceinline__ uint32_t pack_split_h(float x, float y, uint32_t& lo) {
    __half hx = __float2half_rn(x), hy = __float2half_rn(y);
    __half lx = __float2half_rn(x - __half2float(hx));
    __half ly = __float2half_rn(y - __half2float(hy));
    lo = ((uint32_t)__half_as_ushort(ly) << 16) | __half_as_ushort(lx);
    return ((uint32_t)__half_as_ushort(hy) << 16) | __half_as_ushort(hx);
}

// ======================= fp16 NP-pass GEMM (3-stage cp.async + ldmatrix) ====================
#define STGW(MT, NP) ((NP)*(MT)*16 + 128*16)
#define SMEM_PRE(MT, NP) (3 * STGW(MT, NP) * 4)

template<int MT, int NP>
__device__ __forceinline__ void issue_chunk(
    uint32_t stg_base, int kc,
    const __half* Ah, const __half* Al, const __half* B,
    int K, int m0, int n0, int tid)
{
#pragma unroll
    for (int it = 0; it < MT / 64; it++) {
        int lin = tid + it * 256;
        int row = lin >> 2, c = lin & 3;
        int wd = swz(row, c);
        long off = (long)(m0 + row) * K + kc * 32 + c * 8;
        cp16(stg_base + wd * 4, Ah + off, 16);
        if (NP == 2) cp16(stg_base + (MT * 16 + wd) * 4, Al + off, 16);
    }
#pragma unroll
    for (int it = 0; it < 2; it++) {
        int lin = tid + it * 256;
        int row = lin >> 2, c = lin & 3;
        int wd = swz(row, c);
        long off = (long)(n0 + row) * K + kc * 32 + c * 8;
        cp16(stg_base + (NP * MT * 16 + wd) * 4, B + off, 16);
    }
}

template<int MT, int NP>
__global__ __launch_bounds__(256, 2) void mma_pre(
    const __half* __restrict__ Ah, const __half* __restrict__ Al,
    const __half* __restrict__ B,
    int K,
    float* __restrict__ C, __half* __restrict__ Ch, int ldc,
    const float* __restrict__ bias, const float* __restrict__ addsrc, int do_relu)
{
    constexpr int NI = MT / 32;
    extern __shared__ char smem[];
    uint32_t sb0 = (uint32_t)__cvta_generic_to_shared(smem);

    const int tid  = threadIdx.x;
    const int lane = tid & 31;
    const int w    = tid >> 5;
    const int wm   = w >> 2;
    const int wn   = w & 3;
    const int q    = lane >> 2;
    const int s4   = lane & 3;
    const int lrow = lane & 7;
    const int seg  = lane >> 3;
    const int m0   = blockIdx.x * MT;
    const int n0   = blockIdx.y * 128;

    float acc[NI][4][4];
#pragma unroll
    for (int i = 0; i < NI; i++)
#pragma unroll
        for (int j = 0; j < 4; j++)
#pragma unroll
            for (int r = 0; r < 4; r++) acc[i][j][r] = 0.f;

    const int nk = K / 32;
    issue_chunk<MT, NP>(sb0, 0, Ah, Al, B, K, m0, n0, tid);
    CP_COMMIT();
    issue_chunk<MT, NP>(sb0 + STGW(MT, NP) * 4, 1, Ah, Al, B, K, m0, n0, tid);
    CP_COMMIT();

    for (int kt = 0; kt < nk; kt++) {
        CP_WAIT1();
        __syncthreads();

        const uint32_t stg = sb0 + (kt % 3) * STGW(MT, NP) * 4;
        const uint32_t oB  = stg + NP * MT * 16 * 4;

#pragma unroll
        for (int st = 0; st < 2; st++) {
            const int c0 = st * 2;
            const int achk = c0 + (seg >> 1);
            const int aoff = lrow + (seg & 1) * 8;
            const int bchk = c0 + (seg & 1);
            const int bsel = (seg >> 1);

            uint32_t aR[NI][4], bR[4][2];

#pragma unroll
            for (int jp = 0; jp < 2; jp++) {
                int bcol = wn * 32 + (jp * 2 + bsel) * 8 + lrow;
                ldm_x4(bR[jp * 2][0], bR[jp * 2][1], bR[jp * 2 + 1][0], bR[jp * 2 + 1][1],
                       oB + swz(bcol, bchk) * 4);
            }
#pragma unroll
            for (int p = 0; p < NP; p++) {
                const uint32_t oA = stg + p * MT * 16 * 4;
#pragma unroll
                for (int i = 0; i < NI; i++) {
                    int arow = wm * (MT / 2) + i * 16 + aoff;
                    ldm_x4(aR[i][0], aR[i][1], aR[i][2], aR[i][3], oA + swz(arow, achk) * 4);
                }
#pragma unroll
                for (int j = 0; j < 4; j++)
#pragma unroll
                    for (int i = 0; i < NI; i++)
                        mma_f16(acc[i][j], aR[i][0], aR[i][1], aR[i][2], aR[i][3],
                                bR[j][0], bR[j][1]);
            }
        }
        if (kt + 2 < nk)
            issue_chunk<MT, NP>(sb0 + ((kt + 2) % 3) * STGW(MT, NP) * 4, kt + 2,
                                Ah, Al, B, K, m0, n0, tid);
        CP_COMMIT();
    }

    // ---- epilogue ----
#pragma unroll
    for (int i = 0; i < NI; i++) {
        int r0 = m0 + wm * (MT / 2) + i * 16 + q;
#pragma unroll
        for (int j = 0; j < 4; j++) {
            int cc = n0 + wn * 32 + j * 8 + s4 * 2;
            float bx = 0.f, by = 0.f;
            if (bias) { bx = bias[cc]; by = bias[cc + 1]; }
#pragma unroll
            for (int hrow = 0; hrow < 2; hrow++) {
                int rr = r0 + hrow * 8;
                float vx = acc[i][j][hrow * 2 + 0] + bx;
                float vy = acc[i][j][hrow * 2 + 1] + by;
                if (do_relu) { vx = fmaxf(vx, 0.f); vy = fmaxf(vy, 0.f); }
                if (addsrc) {
                    const float2 av = *reinterpret_cast<const float2*>(addsrc + (long)rr * ldc + cc);
                    vx += av.x; vy += av.y;
                }
                if (Ch) {
                    __half2 hv = __floats2half2_rn(vx, vy);
                    *reinterpret_cast<__half2*>(Ch + (long)rr * ldc + cc) = hv;
                } else {
                    *reinterpret_cast<float2*>(C + (long)rr * ldc + cc) = make_float2(vx, vy);
                }
            }
        }
    }
}

// ======================= fp32-input pipelined MMA (center: gather + 3-pass bf16) =============
#define SROW 17
#define SMEM_MMA (512 + 128*256 + 32768 + 2*128*SROW*4 + 2*128*SROW*4)

__global__ __launch_bounds__(256) void mma_gemm_f32(
    const float* __restrict__ A, int lda,
    const float* __restrict__ B, int ldb, long sBz,
    float* __restrict__ C, int ldc, int K,
    const int* __restrict__ rowlists, const int* __restrict__ cnts,
    __half* __restrict__ Ch, __half* __restrict__ Cl)
{
    constexpr int MT = 128;
    constexpr int NI = 4;
    extern __shared__ char smem[];
    int*      rowidx = (int*)smem;
    float*    rawA   = (float*)(smem + 512);
    float*    rawB   = (float*)(smem + 512 + MT * 256);
    uint32_t* sAb    = (uint32_t*)(smem + 512 + MT * 256 + 32768);
    uint32_t* sBb    = sAb + 2 * MT * SROW;

    const int tid  = threadIdx.x;
    const int lane = tid & 31;
    const int w    = tid >> 5;
    const int wm   = w >> 2;
    const int wn   = w & 3;
    const int m0   = blockIdx.x * MT;
    const int n0   = blockIdx.y * 128;
    const int z    = blockIdx.z;

    int rows = cnts[z];
    if (m0 >= rows) return;
    const int* rl = rowlists + z * NN;
    B += z * sBz;

    if (tid < MT) {
        int g = m0 + tid;
        rowidx[tid] = (g < rows) ? rl[g] : -1;
    }
    __syncthreads();

    float acc[NI][4][4];
#pragma unroll
    for (int i = 0; i < NI; i++)
#pragma unroll
        for (int j = 0; j < 4; j++)
#pragma unroll
            for (int r = 0; r < 4; r++) acc[i][j][r] = 0.f;

    const int nk = K / 32;
    {
#pragma unroll
        for (int it = 0; it < NI; it++) {
            int lin = tid + it * 256;
            int row = lin >> 3, f4 = lin & 7;
            int ar = rowidx[row];
            const float* src = (ar >= 0) ? (A + (long)ar * lda + f4 * 4) : A;
            cp16((uint32_t)__cvta_generic_to_shared(rawA + row * 32 + f4 * 4), src,
                 (ar >= 0) ? 16 : 0);
        }
#pragma unroll
        for (int it = 0; it < 4; it++) {
            int lin = tid + it * 256;
            int kk = lin >> 5, n4 = (lin & 31) * 4;
            cp16((uint32_t)__cvta_generic_to_shared(rawB + kk * 128 + n4),
                 B + (long)kk * ldb + n0 + n4, 16);
        }
        CP_COMMIT();
    }

    for (int kt = 0; kt < nk; kt++) {
        const int cur = kt & 1;
        if (kt + 1 < nk) {
            const int nxt = cur ^ 1;
            const int k0 = (kt + 1) * 32;
#pragma unroll
            for (int it = 0; it < NI; it++) {
                int lin = tid + it * 256;
                int row = lin >> 3, f4 = lin & 7;
                int ar = rowidx[row];
                const float* src = (ar >= 0) ? (A + (long)ar * lda + k0 + f4 * 4) : A;
                cp16((uint32_t)__cvta_generic_to_shared(rawA + nxt * MT * 32 + row * 32 + f4 * 4),
                     src, (ar >= 0) ? 16 : 0);
            }
#pragma unroll
            for (int it = 0; it < 4; it++) {
                int lin = tid + it * 256;
                int kk = lin >> 5, n4 = (lin & 31) * 4;
                cp16((uint32_t)__cvta_generic_to_shared(rawB + nxt * 4096 + kk * 128 + n4),
                     B + (long)(k0 + kk) * ldb + n0 + n4, 16);
            }
            CP_COMMIT();
            CP_WAIT1();
        } else {
            CP_WAIT0();
        }
        __syncthreads();

        const float* rA = rawA + cur * MT * 32;
#pragma unroll
        for (int it = 0; it < NI; it++) {
            int lin = tid + it * 256;
            int row = lin >> 3, f4 = lin & 7;
            float4 v = *reinterpret_cast<const float4*>(rA + row * 32 + f4 * 4);
            uint32_t l0, l1;
            uint32_t h0 = pack_split_bf(v.x, v.y, l0);
            uint32_t h1 = pack_split_bf(v.z, v.w, l1);
            int idx = row * SROW + f4 * 2;
            sAb[idx]                 = h0;
            sAb[idx + 1]             = h1;
            sAb[MT * SROW + idx]     = l0;
            sAb[MT * SROW + idx + 1] = l1;
        }
        const float* rB = rawB + cur * 4096;
#pragma unroll
        for (int it = 0; it < 4; it++) {
            int lin = tid + it * 256;
            int kk = lin >> 5, n4 = (lin & 31) * 4;
            float4 v = *reinterpret_cast<const float4*>(rB + kk * 128 + n4);
            float vv[4] = {v.x, v.y, v.z, v.w};
            __nv_bfloat16* pH = reinterpret_cast<__nv_bfloat16*>(sBb);
            __nv_bfloat16* pL = reinterpret_cast<__nv_bfloat16*>(sBb + 128 * SROW);
#pragma unroll
            for (int j = 0; j < 4; j++) {
                __nv_bfloat16 h = __float2bfloat16(vv[j]);
                __nv_bfloat16 l = __float2bfloat16(vv[j] - __bfloat162float(h));
                int bidx = (n4 + j) * (2 * SROW) + kk;
                pH[bidx] = h;
                pL[bidx] = l;
            }
        }
        __syncthreads();

#pragma unroll
        for (int st = 0; st < 2; st++) {
            int k2 = st * 8 + (lane & 3);
            uint32_t a[NI][4];
#pragma unroll
            for (int p = 0; p < 3; p++) {
                const uint32_t* pA = sAb + ((p == 2) ? MT * SROW : 0);
                const uint32_t* pB = sBb + ((p == 1) ? 128 * SROW : 0);
                if (p != 1) {
#pragma unroll
                    for (int i = 0; i < NI; i++) {
                        int r = wm * (MT / 2) + i * 16 + (lane >> 2);
                        a[i][0] = pA[r * SROW + k2];
                        a[i][1] = pA[(r + 8) * SROW + k2];
                        a[i][2] = pA[r * SROW + k2 + 4];
                        a[i][3] = pA[(r + 8) * SROW + k2 + 4];
                    }
                }
#pragma unroll
                for (int j = 0; j < 4; j++) {
                    int c = wn * 32 + j * 8 + (lane >> 2);
                    uint32_t b0 = pB[c * SROW + k2];
                    uint32_t b1 = pB[c * SROW + k2 + 4];
#pragma unroll
                    for (int i = 0; i < NI; i++)
                        mma_bf16(acc[i][j], a[i][0], a[i][1], a[i][2], a[i][3], b0, b1);
                }
            }
        }
    }

    // epilogue: fp32 C + fp16 hi/lo planes (scatter via rowidx)
#pragma unroll
    for (int i = 0; i < NI; i++) {
        int lr0 = wm * (MT / 2) + i * 16 + (lane >> 2);
#pragma unroll
        for (int j = 0; j < 4; j++) {
            int cc = n0 + wn * 32 + j * 8 + (lane & 3) * 2;
#pragma unroll
            for (int hrow = 0; hrow < 2; hrow++) {
                int rr = rowidx[lr0 + hrow * 8];
                if (rr < 0) continue;
                float vx = acc[i][j][hrow * 2 + 0];
                float vy = acc[i][j][hrow * 2 + 1];
                *reinterpret_cast<float2*>(C + (long)rr * ldc + cc) = make_float2(vx, vy);
                uint32_t pl, ph = pack_split_h(vx, vy, pl);
                reinterpret_cast<uint32_t*>(Ch)[((long)rr * ldc + cc) >> 1] = ph;
                reinterpret_cast<uint32_t*>(Cl)[((long)rr * ldc + cc) >> 1] = pl;
            }
        }
    }
}

// ---------------- 32x128x128 SIMT tile (prep GEMMs) ----------------
__device__ __forceinline__ void gemm32(const float* __restrict__ A,
                                       const float* __restrict__ B,
                                       float* __restrict__ Cf32,
                                       float alpha, int transB,
                                       __half* oh, int o_ld, int rowbase, int colbase)
{
    __shared__ float As[32][33];
    __shared__ float Bs[32][128];
    int tid = threadIdx.x, tx = tid & 15, ty = tid >> 4;
    float acc[2][8];
#pragma unroll
    for (int i = 0; i < 2; i++)
#pragma unroll
        for (int j = 0; j < 8; j++) acc[i][j] = 0.f;

    for (int kt = 0; kt < 128; kt += 32) {
#pragma unroll
        for (int j = 0; j < 4; j++) {
            int lin = tid + j * 256;
            int lr = lin >> 5, lc = lin & 31;
            As[lr][lc] = A[lr * 128 + kt + lc];
        }
#pragma unroll
        for (int j = 0; j < 16; j++) {
            int lin = tid + j * 256;
            int br = lin >> 7, bc = lin & 127;
            Bs[br][bc] = transB ? B[bc * 128 + kt + br] : B[(kt + br) * 128 + bc];
        }
        __syncthreads();
#pragma unroll
        for (int kk = 0; kk < 32; kk++) {
            float bv[8];
#pragma unroll
            for (int j = 0; j < 8; j++) bv[j] = Bs[kk][tx + 16 * j];
#pragma unroll
            for (int i = 0; i < 2; i++) {
                float av = As[ty * 2 + i][kk];
#pragma unroll
                for (int j = 0; j < 8; j++) acc[i][j] += av * bv[j];
            }
        }
        __syncthreads();
    }
    if (Cf32) {
#pragma unroll
        for (int i = 0; i < 2; i++)
#pragma unroll
            for (int j = 0; j < 8; j++)
                Cf32[(ty * 2 + i) * 128 + tx + 16 * j] = acc[i][j] * alpha;
    } else {
#pragma unroll
        for (int i = 0; i < 2; i++) {
            int gr = rowbase + ty * 2 + i;
#pragma unroll
            for (int j = 0; j < 8; j++) {
                int gc = colbase + tx + 16 * j;
                oh[(long)gc * o_ld + gr] = __float2half_rn(acc[i][j] * alpha);
            }
        }
    }
}

// prep_fused (128 blocks):
//   blocks 0-63 : phase1 T/S -> barrier -> phase2 BkT/BvT fp16 planes
//   blocks 64-127: barrier -> entity partition (g_cnt zeroed by block 0 pre-barrier)
__global__ __launch_bounds__(256) void prep_fused(const float* __restrict__ rel_w,
                                                  const float* __restrict__ k_w,
                                                  const float* __restrict__ v_w,
                                                  const float* __restrict__ q_w,
                                                  const float* __restrict__ fc_w,
                                                  const int* __restrict__ point_enc)
{
    int b = blockIdx.x;
    int tid = threadIdx.x;

    if (b == 0 && tid < ENTT) g_cnt[tid] = 0;

    if (b < 64) {   // phase 1
        int j = b >> 2, sub = b & 3;
        int r = j & 7, ph = j >> 3;
        const float* A = rel_w + r * (UU * UU) + sub * 32 * UU;
        const float* B = ph ? v_w : k_w;
        float* C = (ph ? g_S : g_T) + r * (UU * UU) + sub * 32 * UU;
        gemm32(A, B, C, 1.f, 0, nullptr, 0, 0, 0);
    }

    // global barrier (monotone ticket: 128 arrivals per replay, no reset needed)
    __syncthreads();
    if (tid == 0) {
        __threadfence();
        int ticket = atomicAdd(&g_bar, 1);
        int target = ((ticket >> 7) + 1) << 7;
        while (atomicAdd(&g_bar, 0) < target) __nanosleep(64);
        __threadfence();
    }
    __syncthreads();

    if (b < 64) {   // phase 2
        int j = b >> 2, sub = b & 3;
        if (j < 8) {
            int r = j;
            gemm32(q_w + sub * 32 * UU, g_T + r * (UU * UU), nullptr,
                   1.f / 128.f, 1, g_BkT, 128, sub * 32, r * UU);
        } else {
            int r = j - 8;
            gemm32(g_S + r * (UU * UU) + sub * 32 * UU, fc_w, nullptr,
                   1.f, 0, g_BvT, 1024, r * UU + sub * 32, 0);
        }
    } else {        // entity partition (64 blocks x 256 = NN threads)
        int n = (b - 64) * 256 + tid;
        int e = point_enc[n];
        int pos = atomicAdd(&g_cnt[e], 1);
        g_lists[e * NN + pos] = n;
    }
}

// ---------------- fused gather / score / softmax / MMA weighted-scatter (fp16) --------------
// xs rows padded to 136 halves (272B): d*68 words mod 32 distinct -> conflict-free ldmatrix.
#define XSP 136

__global__ __launch_bounds__(128) void edge_kernel(const int* __restrict__ adjacency,
                                                   const int* __restrict__ relation)
{
    __shared__ __align__(16) __half xs[DD][XSP];   // gathered neighbor embeddings
    __shared__ __align__(16) __half aw_h[16][32];  // attn, rows 8..15 zero (MMA A pad)
    __shared__ float scores[DD];
    __shared__ int adjs[DD];
    __shared__ int rels[DD];

    int n = blockIdx.x;
    int tid = threadIdx.x, lane = tid & 31, w = tid >> 5;

    if (tid < DD) {
        adjs[tid] = adjacency[n * DD + tid];
        rels[tid] = relation[n * DD + tid];
    }
    __syncthreads();

    // gather x (fp16 hi plane): warp w rows d = w*8..w*8+7, lane stores uint2 (4 halfs)
#pragma unroll
    for (int i = 0; i < 8; i++) {
        int d = w * 8 + i;
        int idx = adjs[d];
        uint2 v = (idx > 0)
            ? reinterpret_cast<const uint2*>(g_center_h + (long)(idx - 1) * UU)[lane]
            : make_uint2(0u, 0u);
        *reinterpret_cast<uint2*>(&xs[d][lane * 4]) = v;
    }
    __syncwarp();

    // scores[d] = qr_h[n, rel[d]] . x[d]
    const __half* qbase = g_qr_h + (long)n * (RR * UU);
#pragma unroll
    for (int i = 0; i < 8; i++) {
        int d = w * 8 + i;
        int r = rels[d];
        const __half2* q2 = reinterpret_cast<const __half2*>(qbase + r * UU);
        float s = 0.f;
#pragma unroll
        for (int k2 = 0; k2 < 2; k2++) {
            int c = lane + 32 * k2;
            float2 qf = __half22float2(q2[c]);
            float2 xf = __half22float2(*reinterpret_cast<const __half2*>(&xs[d][c * 2]));
            s += qf.x * xf.x + qf.y * xf.y;
        }
#pragma unroll
        for (int off = 16; off > 0; off >>= 1) s += __shfl_xor_sync(0xffffffffu, s, off);
        if (lane == 0) scores[d] = (r == 0) ? -1e9f : s;
    }
    __syncthreads();

    // softmax (warp 0) -> aw_h fp16 [16][32], rows 8-15 zero
    if (w == 0) {
        float v = scores[lane];
        float m = v;
#pragma unroll
        for (int off = 16; off > 0; off >>= 1) m = fmaxf(m, __shfl_xor_sync(0xffffffffu, m, off));
        float e = __expf(v - m);
        float sum = e;
#pragma unroll
        for (int off = 16; off > 0; off >>= 1) sum += __shfl_xor_sync(0xffffffffu, sum, off);
        float a = e / sum;
        int r = rels[lane];
#pragma unroll
        for (int rr = 0; rr < 16; rr++)
            aw_h[rr][lane] = __float2half_rn((rr < 8 && r == rr) ? a : 0.f);
    }
    __syncthreads();

    // s[8,128] = aw[8,32] @ xs[32,128] via tensor cores; warp w covers cols w*32..w*32+31
    {
        uint32_t aw_sb = (uint32_t)__cvta_generic_to_shared(&aw_h[0][0]);
        uint32_t xs_sb = (uint32_t)__cvta_generic_to_shared(&xs[0][0]);

        float acc[4][4];
#pragma unroll
        for (int j = 0; j < 4; j++)
#pragma unroll
            for (int r = 0; r < 4; r++) acc[j][r] = 0.f;

#pragma unroll
        for (int st = 0; st < 2; st++) {        // k-steps (d 0-15, 16-31)
            uint32_t a0, a1, a2, a3;
            uint32_t aaddr = aw_sb + (lane & 15) * 64 + st * 32 + (lane >> 4) * 16;
            ldm_x4(a0, a1, a2, a3, aaddr);
            int dd = st * 16 + ((lane >> 3) & 1) * 8 + (lane & 7);
#pragma unroll
            for (int j = 0; j < 4; j++) {
                uint32_t b0, b1;
                uint32_t baddr = xs_sb + dd * (XSP * 2) + (w * 32 + j * 8) * 2;
                ldm_x2_trans(b0, b1, baddr);
                mma_f16(acc[j], a0, a1, a2, a3, b0, b1);
            }
        }

        // D rows 0-7 = relations (regs 0,1); rows 8-15 are padding (regs 2,3 dropped)
        int r = lane >> 2;
        __half* sp = g_sh + (long)n * (RR * UU) + r * UU;
#pragma unroll
        for (int j = 0; j < 4; j++) {
            int c = w * 32 + j * 8 + (lane & 3) * 2;
            __half2 hv = __floats2half2_rn(acc[j][0], acc[j][1]);
            *reinterpret_cast<__half2*>(sp + c) = hv;
        }
    }
}

// ---------------- launch ----------------
extern "C" void kernel_launch(void* const* d_in, const int* in_sizes, int n_in,
                              void* d_out, int out_size)
{
    const float* node_state = (const float*)d_in[0];
    const int*   adjacency  = (const int*)d_in[1];
    const int*   point_enc  = (const int*)d_in[2];
    const int*   relation   = (const int*)d_in[3];
    const float* pe_w       = (const float*)d_in[4];
    const float* rel_w      = (const float*)d_in[5];
    const float* q_w        = (const float*)d_in[6];
    const float* k_w        = (const float*)d_in[7];
    const float* v_w        = (const float*)d_in[8];
    const float* fc_w       = (const float*)d_in[9];
    const float* fc_b       = (const float*)d_in[10];
    float* out = (float*)d_out;

    float *p_center;
    __half *p_ch, *p_cl, *p_qrh, *p_sh, *p_bk, *p_bv;
    int *p_cnt, *p_lists;
    cudaGetSymbolAddress((void**)&p_center, g_center);
    cudaGetSymbolAddress((void**)&p_ch,     g_center_h);
    cudaGetSymbolAddress((void**)&p_cl,     g_center_l);
    cudaGetSymbolAddress((void**)&p_qrh,    g_qr_h);
    cudaGetSymbolAddress((void**)&p_sh,     g_sh);
    cudaGetSymbolAddress((void**)&p_bk,     g_BkT);
    cudaGetSymbolAddress((void**)&p_bv,     g_BvT);
    cudaGetSymbolAddress((void**)&p_cnt,    g_cnt);
    cudaGetSymbolAddress((void**)&p_lists,  g_lists);

    cudaFuncSetAttribute(mma_gemm_f32, cudaFuncAttributeMaxDynamicSharedMemorySize, SMEM_MMA);
    cudaFuncSetAttribute((const void*)mma_pre<128, 2>, cudaFuncAttributeMaxDynamicSharedMemorySize, SMEM_PRE(128, 2));
    cudaFuncSetAttribute((const void*)mma_pre<64, 1>,  cudaFuncAttributeMaxDynamicSharedMemorySize, SMEM_PRE(64, 1));

    // 1. prep + partition (one fused launch): T/S -> barrier -> BkT/BvT | partition
    prep_fused<<<128, 256>>>(rel_w, k_w, v_w, q_w, fc_w, point_enc);

    // 2. center = gathered GEMM (fp32 in, 3-pass bf16); emits fp32 + fp16 hi/lo planes
    mma_gemm_f32<<<dim3(32, 1, 8), 256, SMEM_MMA>>>(
        node_state, INPD, pe_w, 128, (long)INPD * UU,
        p_center, 128, INPD,
        p_lists, p_cnt, p_ch, p_cl);

    // 3. qr = center @ Bk2   (N x 1024, K=128) — fp16 2-pass, fp16 output plane
    mma_pre<128, 2><<<dim3(128, 8), 256, SMEM_PRE(128, 2)>>>(
        p_ch, p_cl, p_bk, 128,
        nullptr, p_qrh, 1024, nullptr, nullptr, 0);

    // 4. fused gather / scores / softmax / MMA weighted sums (fp16 path)
    edge_kernel<<<NN, 128>>>(adjacency, relation);

    // 5. out = center + relu(s @ Bv2 + fc_b)   (N x 128, K=1024) — fp16 1-pass, fp32 out
    mma_pre<64, 1><<<dim3(256, 1), 256, SMEM_PRE(64, 1)>>>(
        p_sh, nullptr, p_bv, 1024,
        out, nullptr, 128, fc_b, p_center, 1);
}